// round 3
// baseline (speedup 1.0000x reference)
#include <cuda_runtime.h>
#include <math.h>
#include <float.h>

// Problem-fixed dims: N=8192, nin=256, nout=128
#define MAXN 8192
#define NIN  256
#define NOUT 128

// Candidate window below global max M of hw2. Softmax weights for
// hw2 < m_row - KEEP are < e^-60 (zero in fp32 reference too). Rows whose
// masked max falls below M-(DELTA_CAND-KEEP) are flagged and recomputed
// exactly by k6 (statistically never happens; correctness guarantee only).
#define DELTA_CAND 260.0f
#define KEEP        60.0f

#define GROUPS   8
#define K5_CHUNK 256   // GROUPS * 32

// -------- device scratch (no allocations allowed) --------
__device__ float g_wv2[NIN];
__device__ float g_hw2[MAXN];
__device__ float g_Mthr;
__device__ int   g_cand_count;
__device__ int   g_flag_count;
__device__ int   g_cand_idx[MAXN];
__device__ float g_cand_e[MAXN];
__device__ float g_hwC[(size_t)MAXN * NOUT];
__device__ int   g_flags[MAXN];

// k1: wv2[k] = w[k,:] . v2   (v2 = v[NOUT:]), also warms w into L2
__global__ void k1_wv2(const float* __restrict__ w, const float* __restrict__ v) {
    int t = threadIdx.x;  // NIN threads
    const float4* wr = (const float4*)(w + (size_t)t * NOUT);
    const float4* v2 = (const float4*)(v + NOUT);
    float a0 = 0.f, a1 = 0.f;
    #pragma unroll 8
    for (int q = 0; q < NOUT / 8; ++q) {
        float4 wa = wr[2 * q], wb = wr[2 * q + 1];
        float4 va = v2[2 * q], vb = v2[2 * q + 1];
        a0 = fmaf(wa.x, va.x, a0); a1 = fmaf(wa.y, va.y, a1);
        a0 = fmaf(wa.z, va.z, a0); a1 = fmaf(wa.w, va.w, a1);
        a0 = fmaf(wb.x, vb.x, a0); a1 = fmaf(wb.y, vb.y, a1);
        a0 = fmaf(wb.z, vb.z, a0); a1 = fmaf(wb.w, vb.w, a1);
    }
    g_wv2[t] = a0 + a1;
}

// k2: hw2[row] = h[row,:] . wv2   (one warp per row, 16 rows/block)
__global__ void k2_hw2(const float* __restrict__ h, int N) {
    __shared__ __align__(16) float s_wv2[NIN];
    int t = threadIdx.x;  // 512
    if (t < NIN) s_wv2[t] = g_wv2[t];
    __syncthreads();
    int row = blockIdx.x * 16 + (t >> 5);
    if (row >= N) return;
    int lane = t & 31;
    const float4* hr = (const float4*)(h + (size_t)row * NIN);
    const float4* wv = (const float4*)s_wv2;
    float4 a = hr[lane], b = hr[lane + 32];
    float4 wa = wv[lane], wb = wv[lane + 32];
    float acc = 0.f;
    acc = fmaf(a.x, wa.x, acc); acc = fmaf(a.y, wa.y, acc);
    acc = fmaf(a.z, wa.z, acc); acc = fmaf(a.w, wa.w, acc);
    acc = fmaf(b.x, wb.x, acc); acc = fmaf(b.y, wb.y, acc);
    acc = fmaf(b.z, wb.z, acc); acc = fmaf(b.w, wb.w, acc);
    for (int d = 16; d; d >>= 1) acc += __shfl_down_sync(0xffffffffu, acc, d);
    if (lane == 0) g_hw2[row] = acc;
}

// k34: single block. Phase A: global max of hw2, deterministic candidate
// compaction, flag/counter clear. Phase B: hwC[c,:] = h[cand[c],:] @ w,
// 8 candidates in flight (thread = (cand, col)).
__global__ void k34_cand_hwC(const float* __restrict__ h, const float* __restrict__ w,
                             int N) {
    __shared__ float s_red[1024];
    __shared__ int   s_wsum[32], s_woff[32];
    __shared__ int   s_cnt;
    __shared__ __align__(16) float s_hc[8][NIN];
    int t = threadIdx.x;  // 1024
    int lane = t & 31, wid = t >> 5;

    // ---- Phase A: max + compaction ----
    float lm = -INFINITY;
    for (int j = t; j < N; j += 1024) lm = fmaxf(lm, g_hw2[j]);
    s_red[t] = lm;
    __syncthreads();
    for (int s = 512; s; s >>= 1) {
        if (t < s) s_red[t] = fmaxf(s_red[t], s_red[t + s]);
        __syncthreads();
    }
    float M = s_red[0];
    __syncthreads();
    float thr = M - DELTA_CAND;
    if (t == 0) { g_Mthr = M - (DELTA_CAND - KEEP); g_flag_count = 0; }

    for (int j = t; j < N; j += 1024) g_flags[j] = 0;

    int per = (N + 1023) >> 10;
    int j0 = t * per;
    int c = 0;
    for (int r = 0; r < per; ++r) {
        int j = j0 + r;
        if (j < N && g_hw2[j] >= thr) c++;
    }
    int inc = c;
    for (int d = 1; d < 32; d <<= 1) {
        int vv = __shfl_up_sync(0xffffffffu, inc, d);
        if (lane >= d) inc += vv;
    }
    if (lane == 31) s_wsum[wid] = inc;
    __syncthreads();
    if (wid == 0) {
        int vv = s_wsum[lane];
        int winc = vv;
        for (int d = 1; d < 32; d <<= 1) {
            int u = __shfl_up_sync(0xffffffffu, winc, d);
            if (lane >= d) winc += u;
        }
        s_woff[lane] = winc - vv;
        if (lane == 31) { g_cand_count = winc; s_cnt = winc; }
    }
    __syncthreads();
    int pos = s_woff[wid] + (inc - c);
    for (int r = 0; r < per; ++r) {
        int j = j0 + r;
        if (j < N && g_hw2[j] >= thr) {
            g_cand_idx[pos] = j;
            g_cand_e[pos]   = g_hw2[j];
            pos++;
        }
    }
    __syncthreads();

    // ---- Phase B: hwC for all candidates, 8 at a time ----
    int cnt = s_cnt;
    for (int cb = 0; cb < cnt; cb += 8) {
        int nrows = min(8, cnt - cb);
        if (t < 64 * nrows) {
            int cc = t >> 6, q = t & 63;  // 64 float4 per 256-float row
            ((float4*)s_hc[cc])[q] =
                ((const float4*)(h + (size_t)g_cand_idx[cb + cc] * NIN))[q];
        }
        __syncthreads();
        int cc = t >> 7, col = t & 127;
        if (cb + cc < cnt) {
            float a0 = 0.f, a1 = 0.f;
            const float* wc = w + col;
            #pragma unroll 8
            for (int kk = 0; kk < NIN; kk += 2) {
                a0 = fmaf(s_hc[cc][kk],     wc[(size_t)kk * NOUT],       a0);
                a1 = fmaf(s_hc[cc][kk + 1], wc[(size_t)(kk + 1) * NOUT], a1);
            }
            g_hwC[(size_t)(cb + cc) * NOUT + col] = a0 + a1;
        }
        __syncthreads();
    }
}

// k5: main kernel. 8 rows/block, one warp per row. Candidates staged in
// 256-entry chunks; per-warp scores live in 8 registers (adj gather has
// MLP=8); nonzero weights visited via ballot+ffs with shfl broadcast.
__global__ void k5_main(const int* __restrict__ adj, float* __restrict__ out, int N) {
    __shared__ int   s_idx[K5_CHUNK];
    __shared__ float s_e[K5_CHUNK];
    int t = threadIdx.x;  // 256
    int r = t >> 5, lane = t & 31;
    int row = blockIdx.x * 8 + r;
    bool active = row < N;

    const int   cnt  = g_cand_count;
    const float Mthr = g_Mthr;
    const int*  adjrow = adj + (size_t)row * N;
    const float4* hwC4 = (const float4*)g_hwC;

    float m = -INFINITY, denom = 0.f;
    float4 acc = make_float4(0.f, 0.f, 0.f, 0.f);

    for (int base = 0; base < cnt; base += K5_CHUNK) {
        int nk = min(K5_CHUNK, cnt - base);
        if (t < nk) { s_idx[t] = g_cand_idx[base + t]; s_e[t] = g_cand_e[base + t]; }
        __syncthreads();

        // gather adj for 8 groups at once (one latency exposure)
        float e[GROUPS];
        #pragma unroll
        for (int g = 0; g < GROUPS; ++g) {
            int k = g * 32 + lane;
            e[g] = -INFINITY;
            if (active && k < nk) {
                int j = s_idx[k];
                if (adjrow[j] > 0) e[g] = s_e[k];
            }
        }
        float cm = e[0];
        #pragma unroll
        for (int g = 1; g < GROUPS; ++g) cm = fmaxf(cm, e[g]);
        for (int d = 16; d; d >>= 1) cm = fmaxf(cm, __shfl_xor_sync(0xffffffffu, cm, d));
        if (cm > m) {
            if (m > -INFINITY) {
                float sc = __expf(m - cm);
                acc.x *= sc; acc.y *= sc; acc.z *= sc; acc.w *= sc;
                denom *= sc;
            }
            m = cm;
        }
        if (m > -INFINITY) {
            float wgt[GROUPS];
            float ls = 0.f;
            #pragma unroll
            for (int g = 0; g < GROUPS; ++g) {
                wgt[g] = __expf(e[g] - m);   // -inf -> 0, no branch
                ls += wgt[g];
            }
            for (int d = 16; d; d >>= 1) ls += __shfl_xor_sync(0xffffffffu, ls, d);
            denom += ls;
            #pragma unroll
            for (int g = 0; g < GROUPS; ++g) {
                unsigned msk = __ballot_sync(0xffffffffu, wgt[g] != 0.f);
                while (msk) {
                    int b = __ffs(msk) - 1;
                    msk &= msk - 1;
                    float wb = __shfl_sync(0xffffffffu, wgt[g], b);
                    float4 hv = hwC4[(size_t)(base + g * 32 + b) * (NOUT / 4) + lane];
                    acc.x = fmaf(wb, hv.x, acc.x);
                    acc.y = fmaf(wb, hv.y, acc.y);
                    acc.z = fmaf(wb, hv.z, acc.z);
                    acc.w = fmaf(wb, hv.w, acc.w);
                }
            }
        }
        __syncthreads();
    }

    if (!active) return;
    bool flag = !(m >= Mthr);
    if (flag && lane == 0) { g_flags[row] = 1; atomicAdd(&g_flag_count, 1); }
    float inv = 1.f / denom;
    float4 o;
    o.x = flag ? 0.f : acc.x * inv;
    o.y = flag ? 0.f : acc.y * inv;
    o.z = flag ? 0.f : acc.z * inv;
    o.w = flag ? 0.f : acc.w * inv;
    ((float4*)out)[(size_t)row * (NOUT / 4) + lane] = o;
}

// k6: exact fallback for flagged rows; whole grid exits on one load when
// no rows were flagged (the statistically-certain case).
__global__ void k6_fallback(const int* __restrict__ adj, const float* __restrict__ h,
                            const float* __restrict__ w, float* __restrict__ out, int N) {
    if (g_flag_count == 0) return;
    int t = threadIdx.x;  // 128
    __shared__ float s_red[128];
    __shared__ int   s_list[512];
    __shared__ float s_wl[512];
    __shared__ int   s_cnt;
    __shared__ float s_h[NIN];

    for (int row = blockIdx.x; row < N; row += gridDim.x) {
        if (!g_flags[row]) continue;
        const int* adjrow = adj + (size_t)row * N;

        float lm = -INFINITY;
        for (int j = t; j < N; j += 128)
            if (adjrow[j] > 0) lm = fmaxf(lm, g_hw2[j]);
        s_red[t] = lm;
        __syncthreads();
        for (int s = 64; s; s >>= 1) {
            if (t < s) s_red[t] = fmaxf(s_red[t], s_red[t + s]);
            __syncthreads();
        }
        float m = s_red[0];
        __syncthreads();
        bool uni = !(m > -INFINITY);  // fully masked row -> uniform softmax

        float acc = 0.f, denom = 0.f;
        for (int cb = 0; cb < N; cb += 512) {
            if (t == 0) s_cnt = 0;
            __syncthreads();
            int ce = min(cb + 512, N);
            for (int j = cb + t; j < ce; j += 128) {
                bool act = uni ? true : (adjrow[j] > 0 && g_hw2[j] >= m - KEEP);
                if (act) {
                    int p = atomicAdd(&s_cnt, 1);
                    s_list[p] = j;
                    s_wl[p]   = uni ? 1.f : expf(g_hw2[j] - m);
                }
            }
            __syncthreads();
            int L = s_cnt;
            for (int l = 0; l < L; ++l) {
                int j = s_list[l];
                float wl = s_wl[l];
                s_h[t]       = h[(size_t)j * NIN + t];
                s_h[t + 128] = h[(size_t)j * NIN + t + 128];
                __syncthreads();
                float dot = 0.f;
                #pragma unroll 8
                for (int kk = 0; kk < NIN; ++kk)
                    dot = fmaf(s_h[kk], w[kk * NOUT + t], dot);
                acc = fmaf(wl, dot, acc);
                denom += wl;
                __syncthreads();
            }
            __syncthreads();
        }
        out[(size_t)row * NOUT + t] = acc / denom;
        __syncthreads();
    }
}

extern "C" void kernel_launch(void* const* d_in, const int* in_sizes, int n_in,
                              void* d_out, int out_size) {
    const float* h   = (const float*)d_in[0];
    const int*   adj = (const int*)d_in[1];
    const float* w   = (const float*)d_in[2];
    const float* v   = (const float*)d_in[3];
    float* out = (float*)d_out;

    int nout = in_sizes[3] / 2;        // 128
    int nin  = in_sizes[2] / nout;     // 256
    int N    = in_sizes[0] / nin;      // 8192
    (void)nout; (void)nin; (void)n_in; (void)out_size;

    k1_wv2<<<1, NIN>>>(w, v);
    k2_hw2<<<(N + 15) / 16, 512>>>(h, N);
    k34_cand_hwC<<<1, 1024>>>(h, w, N);
    k5_main<<<(N + 7) / 8, 256>>>(adj, out, N);
    k6_fallback<<<256, 128>>>(adj, h, w, out, N);
}

// round 4
// speedup vs baseline: 8.3193x; 8.3193x over previous
#include <cuda_runtime.h>
#include <math.h>
#include <float.h>

// Problem-fixed dims: N=8192, nin=256, nout=128
#define MAXN 8192
#define NIN  256
#define NOUT 128

// Candidate window below global max M of hw2 (std ~181, Gumbel scale ~43).
// cnt ~ e^{DELTA/43} ~ 110. Rows whose masked max < M-(DELTA-KEEP) are
// flagged and recomputed exactly by k6 (P ~ 1e-9; correctness guarantee).
// Dropped softmax terms have weight <= e^-KEEP = e^-40 ~ 4e-18 (exact 0 in
// the fp32 reference as well).
#define DELTA_CAND 200.0f
#define KEEP        40.0f

#define GROUPS   8
#define K5_CHUNK 256   // GROUPS * 32

// -------- device scratch (no allocations allowed) --------
__device__ float g_wv2[NIN];
__device__ float g_hw2[MAXN];
__device__ float g_Mthr;
__device__ int   g_cand_count;
__device__ int   g_flag_count;
__device__ int   g_cand_idx[MAXN];
__device__ float g_cand_e[MAXN];
__device__ float g_hwC[(size_t)MAXN * NOUT];
__device__ int   g_flags[MAXN];

// k1: wv2[k] = w[k,:] . v2   (v2 = v[NOUT:]), also warms w into L2
__global__ void k1_wv2(const float* __restrict__ w, const float* __restrict__ v) {
    int t = threadIdx.x;  // NIN threads
    const float4* wr = (const float4*)(w + (size_t)t * NOUT);
    const float4* v2 = (const float4*)(v + NOUT);
    float a0 = 0.f, a1 = 0.f;
    #pragma unroll 8
    for (int q = 0; q < NOUT / 8; ++q) {
        float4 wa = wr[2 * q], wb = wr[2 * q + 1];
        float4 va = v2[2 * q], vb = v2[2 * q + 1];
        a0 = fmaf(wa.x, va.x, a0); a1 = fmaf(wa.y, va.y, a1);
        a0 = fmaf(wa.z, va.z, a0); a1 = fmaf(wa.w, va.w, a1);
        a0 = fmaf(wb.x, vb.x, a0); a1 = fmaf(wb.y, vb.y, a1);
        a0 = fmaf(wb.z, vb.z, a0); a1 = fmaf(wb.w, vb.w, a1);
    }
    g_wv2[t] = a0 + a1;
}

// k2: hw2[row] = h[row,:] . wv2   (one warp per row, 16 rows/block)
__global__ void k2_hw2(const float* __restrict__ h, int N) {
    __shared__ __align__(16) float s_wv2[NIN];
    int t = threadIdx.x;  // 512
    if (t < NIN) s_wv2[t] = g_wv2[t];
    __syncthreads();
    int row = blockIdx.x * 16 + (t >> 5);
    if (row >= N) return;
    int lane = t & 31;
    const float4* hr = (const float4*)(h + (size_t)row * NIN);
    const float4* wv = (const float4*)s_wv2;
    float4 a = hr[lane], b = hr[lane + 32];
    float4 wa = wv[lane], wb = wv[lane + 32];
    float acc = 0.f;
    acc = fmaf(a.x, wa.x, acc); acc = fmaf(a.y, wa.y, acc);
    acc = fmaf(a.z, wa.z, acc); acc = fmaf(a.w, wa.w, acc);
    acc = fmaf(b.x, wb.x, acc); acc = fmaf(b.y, wb.y, acc);
    acc = fmaf(b.z, wb.z, acc); acc = fmaf(b.w, wb.w, acc);
    for (int d = 16; d; d >>= 1) acc += __shfl_down_sync(0xffffffffu, acc, d);
    if (lane == 0) g_hw2[row] = acc;
}

// k3: single block. Global max of hw2, deterministic candidate compaction,
// flag/counter clear. Compaction only — the GEMM lives in k4 (multi-block).
__global__ void k3_candidates(int N) {
    __shared__ float s_red[1024];
    __shared__ int   s_wsum[32], s_woff[32];
    int t = threadIdx.x;  // 1024
    int lane = t & 31, wid = t >> 5;

    float lm = -INFINITY;
    for (int j = t; j < N; j += 1024) lm = fmaxf(lm, g_hw2[j]);
    s_red[t] = lm;
    __syncthreads();
    for (int s = 512; s; s >>= 1) {
        if (t < s) s_red[t] = fmaxf(s_red[t], s_red[t + s]);
        __syncthreads();
    }
    float M = s_red[0];
    __syncthreads();
    float thr = M - DELTA_CAND;
    if (t == 0) { g_Mthr = M - (DELTA_CAND - KEEP); g_flag_count = 0; }

    for (int j = t; j < N; j += 1024) g_flags[j] = 0;

    int per = (N + 1023) >> 10;
    int j0 = t * per;
    int c = 0;
    for (int r = 0; r < per; ++r) {
        int j = j0 + r;
        if (j < N && g_hw2[j] >= thr) c++;
    }
    int inc = c;
    for (int d = 1; d < 32; d <<= 1) {
        int vv = __shfl_up_sync(0xffffffffu, inc, d);
        if (lane >= d) inc += vv;
    }
    if (lane == 31) s_wsum[wid] = inc;
    __syncthreads();
    if (wid == 0) {
        int vv = s_wsum[lane];
        int winc = vv;
        for (int d = 1; d < 32; d <<= 1) {
            int u = __shfl_up_sync(0xffffffffu, winc, d);
            if (lane >= d) winc += u;
        }
        s_woff[lane] = winc - vv;
        if (lane == 31) g_cand_count = winc;
    }
    __syncthreads();
    int pos = s_woff[wid] + (inc - c);
    for (int r = 0; r < per; ++r) {
        int j = j0 + r;
        if (j < N && g_hw2[j] >= thr) {
            g_cand_idx[pos] = j;
            g_cand_e[pos]   = g_hw2[j];
            pos++;
        }
    }
}

// k4: hwC[c,:] = h[cand_idx[c],:] @ w — one candidate per block (grid-stride
// for safety). All working blocks run on distinct SMs in parallel.
__global__ void k4_hwC(const float* __restrict__ h, const float* __restrict__ w) {
    __shared__ __align__(16) float s_h[NIN];
    int cnt = g_cand_count;
    int t = threadIdx.x;  // 128
    for (int c = blockIdx.x; c < cnt; c += gridDim.x) {
        const float4* hr = (const float4*)(h + (size_t)g_cand_idx[c] * NIN);
        if (t < NIN / 4) ((float4*)s_h)[t] = hr[t];
        __syncthreads();
        float a0 = 0.f, a1 = 0.f;
        const float* wc = w + t;
        #pragma unroll 8
        for (int kk = 0; kk < NIN; kk += 2) {
            a0 = fmaf(s_h[kk],     wc[(size_t)kk * NOUT],       a0);
            a1 = fmaf(s_h[kk + 1], wc[(size_t)(kk + 1) * NOUT], a1);
        }
        g_hwC[(size_t)c * NOUT + t] = a0 + a1;
        __syncthreads();
    }
}

// k5: main kernel. 8 rows/block, one warp per row. Candidates staged in
// 256-entry chunks; per-warp scores live in 8 registers (adj gather has
// MLP=8); nonzero weights visited via ballot+ffs with shfl broadcast.
__global__ void k5_main(const int* __restrict__ adj, float* __restrict__ out, int N) {
    __shared__ int   s_idx[K5_CHUNK];
    __shared__ float s_e[K5_CHUNK];
    int t = threadIdx.x;  // 256
    int r = t >> 5, lane = t & 31;
    int row = blockIdx.x * 8 + r;
    bool active = row < N;

    const int   cnt  = g_cand_count;
    const float Mthr = g_Mthr;
    const int*  adjrow = adj + (size_t)row * N;
    const float4* hwC4 = (const float4*)g_hwC;

    float m = -INFINITY, denom = 0.f;
    float4 acc = make_float4(0.f, 0.f, 0.f, 0.f);

    for (int base = 0; base < cnt; base += K5_CHUNK) {
        int nk = min(K5_CHUNK, cnt - base);
        if (t < nk) { s_idx[t] = g_cand_idx[base + t]; s_e[t] = g_cand_e[base + t]; }
        __syncthreads();

        // gather adj for 8 groups at once (one latency exposure, MLP=8)
        float e[GROUPS];
        #pragma unroll
        for (int g = 0; g < GROUPS; ++g) {
            int k = g * 32 + lane;
            e[g] = -INFINITY;
            if (active && k < nk) {
                int j = s_idx[k];
                if (adjrow[j] > 0) e[g] = s_e[k];
            }
        }
        float cm = e[0];
        #pragma unroll
        for (int g = 1; g < GROUPS; ++g) cm = fmaxf(cm, e[g]);
        for (int d = 16; d; d >>= 1) cm = fmaxf(cm, __shfl_xor_sync(0xffffffffu, cm, d));
        if (cm > m) {
            if (m > -INFINITY) {
                float sc = __expf(m - cm);
                acc.x *= sc; acc.y *= sc; acc.z *= sc; acc.w *= sc;
                denom *= sc;
            }
            m = cm;
        }
        if (m > -INFINITY) {
            float wgt[GROUPS];
            float ls = 0.f;
            #pragma unroll
            for (int g = 0; g < GROUPS; ++g) {
                wgt[g] = __expf(e[g] - m);   // -inf -> 0, no branch
                ls += wgt[g];
            }
            for (int d = 16; d; d >>= 1) ls += __shfl_xor_sync(0xffffffffu, ls, d);
            denom += ls;
            #pragma unroll
            for (int g = 0; g < GROUPS; ++g) {
                unsigned msk = __ballot_sync(0xffffffffu, wgt[g] != 0.f);
                while (msk) {
                    int b = __ffs(msk) - 1;
                    msk &= msk - 1;
                    float wb = __shfl_sync(0xffffffffu, wgt[g], b);
                    float4 hv = hwC4[(size_t)(base + g * 32 + b) * (NOUT / 4) + lane];
                    acc.x = fmaf(wb, hv.x, acc.x);
                    acc.y = fmaf(wb, hv.y, acc.y);
                    acc.z = fmaf(wb, hv.z, acc.z);
                    acc.w = fmaf(wb, hv.w, acc.w);
                }
            }
        }
        __syncthreads();
    }

    if (!active) return;
    bool flag = !(m >= Mthr);
    if (flag && lane == 0) { g_flags[row] = 1; atomicAdd(&g_flag_count, 1); }
    float inv = 1.f / denom;
    float4 o;
    o.x = flag ? 0.f : acc.x * inv;
    o.y = flag ? 0.f : acc.y * inv;
    o.z = flag ? 0.f : acc.z * inv;
    o.w = flag ? 0.f : acc.w * inv;
    ((float4*)out)[(size_t)row * (NOUT / 4) + lane] = o;
}

// k6: exact fallback for flagged rows; whole grid exits on one load when
// no rows were flagged (the statistically-certain case).
__global__ void k6_fallback(const int* __restrict__ adj, const float* __restrict__ h,
                            const float* __restrict__ w, float* __restrict__ out, int N) {
    if (g_flag_count == 0) return;
    int t = threadIdx.x;  // 128
    __shared__ float s_red[128];
    __shared__ int   s_list[512];
    __shared__ float s_wl[512];
    __shared__ int   s_cnt;
    __shared__ float s_h[NIN];

    for (int row = blockIdx.x; row < N; row += gridDim.x) {
        if (!g_flags[row]) continue;
        const int* adjrow = adj + (size_t)row * N;

        float lm = -INFINITY;
        for (int j = t; j < N; j += 128)
            if (adjrow[j] > 0) lm = fmaxf(lm, g_hw2[j]);
        s_red[t] = lm;
        __syncthreads();
        for (int s = 64; s; s >>= 1) {
            if (t < s) s_red[t] = fmaxf(s_red[t], s_red[t + s]);
            __syncthreads();
        }
        float m = s_red[0];
        __syncthreads();
        bool uni = !(m > -INFINITY);  // fully masked row -> uniform softmax

        float acc = 0.f, denom = 0.f;
        for (int cb = 0; cb < N; cb += 512) {
            if (t == 0) s_cnt = 0;
            __syncthreads();
            int ce = min(cb + 512, N);
            for (int j = cb + t; j < ce; j += 128) {
                bool act = uni ? true : (adjrow[j] > 0 && g_hw2[j] >= m - KEEP);
                if (act) {
                    int p = atomicAdd(&s_cnt, 1);
                    s_list[p] = j;
                    s_wl[p]   = uni ? 1.f : expf(g_hw2[j] - m);
                }
            }
            __syncthreads();
            int L = s_cnt;
            for (int l = 0; l < L; ++l) {
                int j = s_list[l];
                float wl = s_wl[l];
                s_h[t]       = h[(size_t)j * NIN + t];
                s_h[t + 128] = h[(size_t)j * NIN + t + 128];
                __syncthreads();
                float dot = 0.f;
                #pragma unroll 8
                for (int kk = 0; kk < NIN; ++kk)
                    dot = fmaf(s_h[kk], w[kk * NOUT + t], dot);
                acc = fmaf(wl, dot, acc);
                denom += wl;
                __syncthreads();
            }
            __syncthreads();
        }
        out[(size_t)row * NOUT + t] = acc / denom;
        __syncthreads();
    }
}

extern "C" void kernel_launch(void* const* d_in, const int* in_sizes, int n_in,
                              void* d_out, int out_size) {
    const float* h   = (const float*)d_in[0];
    const int*   adj = (const int*)d_in[1];
    const float* w   = (const float*)d_in[2];
    const float* v   = (const float*)d_in[3];
    float* out = (float*)d_out;

    int nout = in_sizes[3] / 2;        // 128
    int nin  = in_sizes[2] / nout;     // 256
    int N    = in_sizes[0] / nin;      // 8192
    (void)nout; (void)nin; (void)n_in; (void)out_size;

    k1_wv2<<<1, NIN>>>(w, v);
    k2_hw2<<<(N + 15) / 16, 512>>>(h, N);
    k3_candidates<<<1, 1024>>>(N);
    k4_hwC<<<1024, 128>>>(h, w);
    k5_main<<<(N + 7) / 8, 256>>>(adj, out, N);
    k6_fallback<<<256, 128>>>(adj, h, w, out, N);
}

// round 7
// speedup vs baseline: 8.5513x; 1.0279x over previous
#include <cuda_runtime.h>
#include <math.h>
#include <float.h>

// Problem-fixed dims: N=8192, nin=256, nout=128
#define MAXN 8192
#define NIN  256
#define NOUT 128

// Candidate window below global max M of hw2 (std ~181, Gumbel scale ~43).
// cnt ~ e^{DELTA/43} ~ 110. Rows whose masked max < M-(DELTA-KEEP) are
// flagged and recomputed exactly by k6 (P ~ 1e-9; correctness guarantee).
// Dropped softmax terms have weight <= e^-KEEP = e^-40 ~ 4e-18 (exact 0 in
// the fp32 reference as well).
#define DELTA_CAND 200.0f
#define KEEP        40.0f

#define GROUPS   8
#define K5_CHUNK 256   // GROUPS * 32

// -------- device scratch (no allocations allowed) --------
__device__ float g_wv2[NIN];
__device__ float g_hw2[MAXN];
__device__ float g_Mthr;
__device__ int   g_cand_count;
__device__ int   g_flag_count;
__device__ int   g_cand_idx[MAXN];
__device__ float g_cand_e[MAXN];
__device__ float g_hwC[(size_t)MAXN * NOUT];
__device__ int   g_flags[MAXN];

// k1: wv2[k] = w[k,:] . v2   (v2 = v[NOUT:]), also warms w into L2
__global__ void k1_wv2(const float* __restrict__ w, const float* __restrict__ v) {
    int t = threadIdx.x;  // NIN threads
    const float4* wr = (const float4*)(w + (size_t)t * NOUT);
    const float4* v2 = (const float4*)(v + NOUT);
    float a0 = 0.f, a1 = 0.f;
    #pragma unroll 8
    for (int q = 0; q < NOUT / 8; ++q) {
        float4 wa = wr[2 * q], wb = wr[2 * q + 1];
        float4 va = v2[2 * q], vb = v2[2 * q + 1];
        a0 = fmaf(wa.x, va.x, a0); a1 = fmaf(wa.y, va.y, a1);
        a0 = fmaf(wa.z, va.z, a0); a1 = fmaf(wa.w, va.w, a1);
        a0 = fmaf(wb.x, vb.x, a0); a1 = fmaf(wb.y, vb.y, a1);
        a0 = fmaf(wb.z, vb.z, a0); a1 = fmaf(wb.w, vb.w, a1);
    }
    g_wv2[t] = a0 + a1;
}

// k2: hw2[row] = h[row,:] . wv2   (one warp per row, 16 rows/block)
__global__ void k2_hw2(const float* __restrict__ h, int N) {
    __shared__ __align__(16) float s_wv2[NIN];
    int t = threadIdx.x;  // 512
    if (t < NIN) s_wv2[t] = g_wv2[t];
    __syncthreads();
    int row = blockIdx.x * 16 + (t >> 5);
    if (row >= N) return;
    int lane = t & 31;
    const float4* hr = (const float4*)(h + (size_t)row * NIN);
    const float4* wv = (const float4*)s_wv2;
    float4 a = hr[lane], b = hr[lane + 32];
    float4 wa = wv[lane], wb = wv[lane + 32];
    float acc = 0.f;
    acc = fmaf(a.x, wa.x, acc); acc = fmaf(a.y, wa.y, acc);
    acc = fmaf(a.z, wa.z, acc); acc = fmaf(a.w, wa.w, acc);
    acc = fmaf(b.x, wb.x, acc); acc = fmaf(b.y, wb.y, acc);
    acc = fmaf(b.z, wb.z, acc); acc = fmaf(b.w, wb.w, acc);
    for (int d = 16; d; d >>= 1) acc += __shfl_down_sync(0xffffffffu, acc, d);
    if (lane == 0) g_hw2[row] = acc;
}

// k3: single block. Global max of hw2, deterministic candidate compaction,
// flag/counter clear. Compaction only — the GEMM lives in k4 (multi-block).
__global__ void k3_candidates(int N) {
    __shared__ float s_red[1024];
    __shared__ int   s_wsum[32], s_woff[32];
    int t = threadIdx.x;  // 1024
    int lane = t & 31, wid = t >> 5;

    float lm = -INFINITY;
    for (int j = t; j < N; j += 1024) lm = fmaxf(lm, g_hw2[j]);
    s_red[t] = lm;
    __syncthreads();
    for (int s = 512; s; s >>= 1) {
        if (t < s) s_red[t] = fmaxf(s_red[t], s_red[t + s]);
        __syncthreads();
    }
    float M = s_red[0];
    __syncthreads();
    float thr = M - DELTA_CAND;
    if (t == 0) { g_Mthr = M - (DELTA_CAND - KEEP); g_flag_count = 0; }

    for (int j = t; j < N; j += 1024) g_flags[j] = 0;

    int per = (N + 1023) >> 10;
    int j0 = t * per;
    int c = 0;
    for (int r = 0; r < per; ++r) {
        int j = j0 + r;
        if (j < N && g_hw2[j] >= thr) c++;
    }
    int inc = c;
    for (int d = 1; d < 32; d <<= 1) {
        int vv = __shfl_up_sync(0xffffffffu, inc, d);
        if (lane >= d) inc += vv;
    }
    if (lane == 31) s_wsum[wid] = inc;
    __syncthreads();
    if (wid == 0) {
        int vv = s_wsum[lane];
        int winc = vv;
        for (int d = 1; d < 32; d <<= 1) {
            int u = __shfl_up_sync(0xffffffffu, winc, d);
            if (lane >= d) winc += u;
        }
        s_woff[lane] = winc - vv;
        if (lane == 31) g_cand_count = winc;
    }
    __syncthreads();
    int pos = s_woff[wid] + (inc - c);
    for (int r = 0; r < per; ++r) {
        int j = j0 + r;
        if (j < N && g_hw2[j] >= thr) {
            g_cand_idx[pos] = j;
            g_cand_e[pos]   = g_hw2[j];
            pos++;
        }
    }
}

// k4: hwC[c,:] = h[cand_idx[c],:] @ w — one candidate per block, 128 threads
// (thread = output col). Fully-unrolled 16-wide load batches force ptxas to
// keep many LDGs in flight (last profile: regs=31 -> MLP~2 -> 310 cyc/iter).
__global__ void k4_hwC(const float* __restrict__ h, const float* __restrict__ w) {
    __shared__ __align__(16) float s_h[NIN];
    int cnt = g_cand_count;
    int t = threadIdx.x;  // 128
    for (int c = blockIdx.x; c < cnt; c += gridDim.x) {
        if (t < NIN / 4)
            ((float4*)s_h)[t] = ((const float4*)(h + (size_t)g_cand_idx[c] * NIN))[t];
        __syncthreads();
        const float* wc = w + t;
        float a0 = 0.f, a1 = 0.f, a2 = 0.f, a3 = 0.f;
        #pragma unroll
        for (int b = 0; b < NIN / 16; ++b) {
            float wv[16];
            #pragma unroll
            for (int u = 0; u < 16; ++u)
                wv[u] = wc[(size_t)(b * 16 + u) * NOUT];
            float hv[16];
            #pragma unroll
            for (int u = 0; u < 16; ++u)
                hv[u] = s_h[b * 16 + u];
            #pragma unroll
            for (int u = 0; u < 16; u += 4) {
                a0 = fmaf(hv[u],     wv[u],     a0);
                a1 = fmaf(hv[u + 1], wv[u + 1], a1);
                a2 = fmaf(hv[u + 2], wv[u + 2], a2);
                a3 = fmaf(hv[u + 3], wv[u + 3], a3);
            }
        }
        g_hwC[(size_t)c * NOUT + t] = (a0 + a1) + (a2 + a3);
        __syncthreads();
    }
}

// k5: main kernel. 8 rows/block, one warp per row. Candidates staged in
// 256-entry chunks; per-warp scores live in 8 registers (adj gather has
// MLP=8); nonzero weights visited via ballot+ffs with shfl broadcast.
__global__ void k5_main(const int* __restrict__ adj, float* __restrict__ out, int N) {
    __shared__ int   s_idx[K5_CHUNK];
    __shared__ float s_e[K5_CHUNK];
    int t = threadIdx.x;  // 256
    int r = t >> 5, lane = t & 31;
    int row = blockIdx.x * 8 + r;
    bool active = row < N;

    const int   cnt  = g_cand_count;
    const float Mthr = g_Mthr;
    const int*  adjrow = adj + (size_t)row * N;
    const float4* hwC4 = (const float4*)g_hwC;

    float m = -INFINITY, denom = 0.f;
    float4 acc = make_float4(0.f, 0.f, 0.f, 0.f);

    for (int base = 0; base < cnt; base += K5_CHUNK) {
        int nk = min(K5_CHUNK, cnt - base);
        if (t < nk) { s_idx[t] = g_cand_idx[base + t]; s_e[t] = g_cand_e[base + t]; }
        __syncthreads();

        // gather adj for 8 groups at once (one latency exposure, MLP=8)
        float e[GROUPS];
        #pragma unroll
        for (int g = 0; g < GROUPS; ++g) {
            int k = g * 32 + lane;
            e[g] = -INFINITY;
            if (active && k < nk) {
                int j = s_idx[k];
                if (adjrow[j] > 0) e[g] = s_e[k];
            }
        }
        float cm = e[0];
        #pragma unroll
        for (int g = 1; g < GROUPS; ++g) cm = fmaxf(cm, e[g]);
        for (int d = 16; d; d >>= 1) cm = fmaxf(cm, __shfl_xor_sync(0xffffffffu, cm, d));
        if (cm > m) {
            if (m > -INFINITY) {
                float sc = __expf(m - cm);
                acc.x *= sc; acc.y *= sc; acc.z *= sc; acc.w *= sc;
                denom *= sc;
            }
            m = cm;
        }
        if (m > -INFINITY) {
            float wgt[GROUPS];
            float ls = 0.f;
            #pragma unroll
            for (int g = 0; g < GROUPS; ++g) {
                wgt[g] = __expf(e[g] - m);   // -inf -> 0, no branch
                ls += wgt[g];
            }
            for (int d = 16; d; d >>= 1) ls += __shfl_xor_sync(0xffffffffu, ls, d);
            denom += ls;
            #pragma unroll
            for (int g = 0; g < GROUPS; ++g) {
                unsigned msk = __ballot_sync(0xffffffffu, wgt[g] != 0.f);
                while (msk) {
                    int b = __ffs(msk) - 1;
                    msk &= msk - 1;
                    float wb = __shfl_sync(0xffffffffu, wgt[g], b);
                    float4 hv = hwC4[(size_t)(base + g * 32 + b) * (NOUT / 4) + lane];
                    acc.x = fmaf(wb, hv.x, acc.x);
                    acc.y = fmaf(wb, hv.y, acc.y);
                    acc.z = fmaf(wb, hv.z, acc.z);
                    acc.w = fmaf(wb, hv.w, acc.w);
                }
            }
        }
        __syncthreads();
    }

    if (!active) return;
    bool flag = !(m >= Mthr);
    if (flag && lane == 0) { g_flags[row] = 1; atomicAdd(&g_flag_count, 1); }
    float inv = 1.f / denom;
    float4 o;
    o.x = flag ? 0.f : acc.x * inv;
    o.y = flag ? 0.f : acc.y * inv;
    o.z = flag ? 0.f : acc.z * inv;
    o.w = flag ? 0.f : acc.w * inv;
    ((float4*)out)[(size_t)row * (NOUT / 4) + lane] = o;
}

// k6: exact fallback for flagged rows; whole grid exits on one load when
// no rows were flagged (the statistically-certain case).
__global__ void k6_fallback(const int* __restrict__ adj, const float* __restrict__ h,
                            const float* __restrict__ w, float* __restrict__ out, int N) {
    if (g_flag_count == 0) return;
    int t = threadIdx.x;  // 128
    __shared__ float s_red[128];
    __shared__ int   s_list[512];
    __shared__ float s_wl[512];
    __shared__ int   s_cnt;
    __shared__ float s_h[NIN];

    for (int row = blockIdx.x; row < N; row += gridDim.x) {
        if (!g_flags[row]) continue;
        const int* adjrow = adj + (size_t)row * N;

        float lm = -INFINITY;
        for (int j = t; j < N; j += 128)
            if (adjrow[j] > 0) lm = fmaxf(lm, g_hw2[j]);
        s_red[t] = lm;
        __syncthreads();
        for (int s = 64; s; s >>= 1) {
            if (t < s) s_red[t] = fmaxf(s_red[t], s_red[t + s]);
            __syncthreads();
        }
        float m = s_red[0];
        __syncthreads();
        bool uni = !(m > -INFINITY);  // fully masked row -> uniform softmax

        float acc = 0.f, denom = 0.f;
        for (int cb = 0; cb < N; cb += 512) {
            if (t == 0) s_cnt = 0;
            __syncthreads();
            int ce = min(cb + 512, N);
            for (int j = cb + t; j < ce; j += 128) {
                bool act = uni ? true : (adjrow[j] > 0 && g_hw2[j] >= m - KEEP);
                if (act) {
                    int p = atomicAdd(&s_cnt, 1);
                    s_list[p] = j;
                    s_wl[p]   = uni ? 1.f : expf(g_hw2[j] - m);
                }
            }
            __syncthreads();
            int L = s_cnt;
            for (int l = 0; l < L; ++l) {
                int j = s_list[l];
                float wl = s_wl[l];
                s_h[t]       = h[(size_t)j * NIN + t];
                s_h[t + 128] = h[(size_t)j * NIN + t + 128];
                __syncthreads();
                float dot = 0.f;
                #pragma unroll 8
                for (int kk = 0; kk < NIN; ++kk)
                    dot = fmaf(s_h[kk], w[kk * NOUT + t], dot);
                acc = fmaf(wl, dot, acc);
                denom += wl;
                __syncthreads();
            }
            __syncthreads();
        }
        out[(size_t)row * NOUT + t] = acc / denom;
        __syncthreads();
    }
}

extern "C" void kernel_launch(void* const* d_in, const int* in_sizes, int n_in,
                              void* d_out, int out_size) {
    const float* h   = (const float*)d_in[0];
    const int*   adj = (const int*)d_in[1];
    const float* w   = (const float*)d_in[2];
    const float* v   = (const float*)d_in[3];
    float* out = (float*)d_out;

    int nout = in_sizes[3] / 2;        // 128
    int nin  = in_sizes[2] / nout;     // 256
    int N    = in_sizes[0] / nin;      // 8192
    (void)nout; (void)nin; (void)n_in; (void)out_size;

    k1_wv2<<<1, NIN>>>(w, v);
    k2_hw2<<<(N + 15) / 16, 512>>>(h, N);
    k3_candidates<<<1, 1024>>>(N);
    k4_hwC<<<256, 128>>>(h, w);
    k5_main<<<(N + 7) / 8, 256>>>(adj, out, N);
    k6_fallback<<<256, 128>>>(adj, h, w, out, N);
}

// round 8
// speedup vs baseline: 9.5394x; 1.1156x over previous
#include <cuda_runtime.h>
#include <math.h>
#include <float.h>

// Problem-fixed dims: N=8192, nin=256, nout=128
#define MAXN 8192
#define NIN  256
#define NOUT 128

// Candidate window below global max M of hw2 (std ~181, Gumbel scale ~43).
// cnt ~ e^{DELTA/43} ~ 110. Rows whose masked max < M-(DELTA-KEEP) are
// flagged and recomputed exactly by k6 (P ~ 1e-9; correctness guarantee).
// Dropped softmax terms have weight <= e^-KEEP = e^-40 ~ 4e-18 (exact 0 in
// the fp32 reference as well).
#define DELTA_CAND 200.0f
#define KEEP        40.0f

#define GROUPS   8
#define K5_CHUNK 256   // GROUPS * 32

// -------- device scratch (no allocations allowed) --------
__device__ float g_wv2[NIN];
__device__ float g_hw2[MAXN];
__device__ float g_Mthr;
__device__ int   g_cand_count;
__device__ int   g_flag_count;
__device__ int   g_cand_idx[MAXN];
__device__ float g_cand_e[MAXN];
__device__ float g_hwC[(size_t)MAXN * NOUT];
__device__ int   g_flags[MAXN];

// k1: wv2[k] = w[k,:] . v2   (v2 = v[NOUT:]), also warms w into L2
__global__ void k1_wv2(const float* __restrict__ w, const float* __restrict__ v) {
    int t = threadIdx.x;  // NIN threads
    const float4* wr = (const float4*)(w + (size_t)t * NOUT);
    const float4* v2 = (const float4*)(v + NOUT);
    float a0 = 0.f, a1 = 0.f;
    #pragma unroll 8
    for (int q = 0; q < NOUT / 8; ++q) {
        float4 wa = wr[2 * q], wb = wr[2 * q + 1];
        float4 va = v2[2 * q], vb = v2[2 * q + 1];
        a0 = fmaf(wa.x, va.x, a0); a1 = fmaf(wa.y, va.y, a1);
        a0 = fmaf(wa.z, va.z, a0); a1 = fmaf(wa.w, va.w, a1);
        a0 = fmaf(wb.x, vb.x, a0); a1 = fmaf(wb.y, vb.y, a1);
        a0 = fmaf(wb.z, vb.z, a0); a1 = fmaf(wb.w, vb.w, a1);
    }
    g_wv2[t] = a0 + a1;
}

// k2: hw2[row] = h[row,:] . wv2   (one warp per row, 16 rows/block)
__global__ void k2_hw2(const float* __restrict__ h, int N) {
    __shared__ __align__(16) float s_wv2[NIN];
    int t = threadIdx.x;  // 512
    if (t < NIN) s_wv2[t] = g_wv2[t];
    __syncthreads();
    int row = blockIdx.x * 16 + (t >> 5);
    if (row >= N) return;
    int lane = t & 31;
    const float4* hr = (const float4*)(h + (size_t)row * NIN);
    const float4* wv = (const float4*)s_wv2;
    float4 a = hr[lane], b = hr[lane + 32];
    float4 wa = wv[lane], wb = wv[lane + 32];
    float acc = 0.f;
    acc = fmaf(a.x, wa.x, acc); acc = fmaf(a.y, wa.y, acc);
    acc = fmaf(a.z, wa.z, acc); acc = fmaf(a.w, wa.w, acc);
    acc = fmaf(b.x, wb.x, acc); acc = fmaf(b.y, wb.y, acc);
    acc = fmaf(b.z, wb.z, acc); acc = fmaf(b.w, wb.w, acc);
    for (int d = 16; d; d >>= 1) acc += __shfl_down_sync(0xffffffffu, acc, d);
    if (lane == 0) g_hw2[row] = acc;
}

// k3: single block. Global max of hw2, deterministic candidate compaction,
// flag/counter clear. Compaction only — the GEMM lives in k4 (multi-block).
__global__ void k3_candidates(int N) {
    __shared__ float s_red[1024];
    __shared__ int   s_wsum[32], s_woff[32];
    int t = threadIdx.x;  // 1024
    int lane = t & 31, wid = t >> 5;

    float lm = -INFINITY;
    for (int j = t; j < N; j += 1024) lm = fmaxf(lm, g_hw2[j]);
    s_red[t] = lm;
    __syncthreads();
    for (int s = 512; s; s >>= 1) {
        if (t < s) s_red[t] = fmaxf(s_red[t], s_red[t + s]);
        __syncthreads();
    }
    float M = s_red[0];
    __syncthreads();
    float thr = M - DELTA_CAND;
    if (t == 0) { g_Mthr = M - (DELTA_CAND - KEEP); g_flag_count = 0; }

    for (int j = t; j < N; j += 1024) g_flags[j] = 0;

    int per = (N + 1023) >> 10;
    int j0 = t * per;
    int c = 0;
    for (int r = 0; r < per; ++r) {
        int j = j0 + r;
        if (j < N && g_hw2[j] >= thr) c++;
    }
    int inc = c;
    for (int d = 1; d < 32; d <<= 1) {
        int vv = __shfl_up_sync(0xffffffffu, inc, d);
        if (lane >= d) inc += vv;
    }
    if (lane == 31) s_wsum[wid] = inc;
    __syncthreads();
    if (wid == 0) {
        int vv = s_wsum[lane];
        int winc = vv;
        for (int d = 1; d < 32; d <<= 1) {
            int u = __shfl_up_sync(0xffffffffu, winc, d);
            if (lane >= d) winc += u;
        }
        s_woff[lane] = winc - vv;
        if (lane == 31) g_cand_count = winc;
    }
    __syncthreads();
    int pos = s_woff[wid] + (inc - c);
    for (int r = 0; r < per; ++r) {
        int j = j0 + r;
        if (j < N && g_hw2[j] >= thr) {
            g_cand_idx[pos] = j;
            g_cand_e[pos]   = g_hw2[j];
            pos++;
        }
    }
}

// k4 v2: hwC[c,:] = h[cand_idx[c],:] @ w. One candidate per block iteration,
// 1024 threads = 8 K-groups x 128 cols. Each thread issues only 32 w-loads
// (serial-chain cap: even at ptxas MLP=2 that's ~3.8K cyc, vs 30K before);
// K-partials reduced through shared memory.
__global__ void __launch_bounds__(1024, 1)
k4_hwC(const float* __restrict__ h, const float* __restrict__ w) {
    __shared__ __align__(16) float s_h[NIN];
    __shared__ float s_part[8][NOUT];
    int cnt = g_cand_count;
    int t = threadIdx.x;           // 1024
    int col = t & 127, kg = t >> 7; // kg in [0,8)
    for (int c = blockIdx.x; c < cnt; c += gridDim.x) {
        if (t < NIN / 4)
            ((float4*)s_h)[t] = ((const float4*)(h + (size_t)g_cand_idx[c] * NIN))[t];
        __syncthreads();
        const float* wc = w + (size_t)(kg * 32) * NOUT + col;
        float a0 = 0.f, a1 = 0.f, a2 = 0.f, a3 = 0.f;
        #pragma unroll
        for (int b = 0; b < 2; ++b) {
            float wv[16];
            #pragma unroll
            for (int u = 0; u < 16; ++u)
                wv[u] = wc[(size_t)(b * 16 + u) * NOUT];
            #pragma unroll
            for (int u = 0; u < 16; u += 4) {
                a0 = fmaf(s_h[kg * 32 + b * 16 + u],     wv[u],     a0);
                a1 = fmaf(s_h[kg * 32 + b * 16 + u + 1], wv[u + 1], a1);
                a2 = fmaf(s_h[kg * 32 + b * 16 + u + 2], wv[u + 2], a2);
                a3 = fmaf(s_h[kg * 32 + b * 16 + u + 3], wv[u + 3], a3);
            }
        }
        s_part[kg][col] = (a0 + a1) + (a2 + a3);
        __syncthreads();
        if (t < NOUT) {
            float s = 0.f;
            #pragma unroll
            for (int g = 0; g < 8; ++g) s += s_part[g][t];
            g_hwC[(size_t)c * NOUT + t] = s;
        }
        __syncthreads();
    }
}

// k5: main kernel. 8 rows/block, one warp per row. Candidates staged in
// 256-entry chunks; per-warp scores live in 8 registers (adj gather has
// MLP=8); nonzero weights visited via ballot+ffs with shfl broadcast.
__global__ void k5_main(const int* __restrict__ adj, float* __restrict__ out, int N) {
    __shared__ int   s_idx[K5_CHUNK];
    __shared__ float s_e[K5_CHUNK];
    int t = threadIdx.x;  // 256
    int r = t >> 5, lane = t & 31;
    int row = blockIdx.x * 8 + r;
    bool active = row < N;

    const int   cnt  = g_cand_count;
    const float Mthr = g_Mthr;
    const int*  adjrow = adj + (size_t)row * N;
    const float4* hwC4 = (const float4*)g_hwC;

    float m = -INFINITY, denom = 0.f;
    float4 acc = make_float4(0.f, 0.f, 0.f, 0.f);

    for (int base = 0; base < cnt; base += K5_CHUNK) {
        int nk = min(K5_CHUNK, cnt - base);
        if (t < nk) { s_idx[t] = g_cand_idx[base + t]; s_e[t] = g_cand_e[base + t]; }
        __syncthreads();

        // gather adj for 8 groups at once (one latency exposure, MLP=8)
        float e[GROUPS];
        #pragma unroll
        for (int g = 0; g < GROUPS; ++g) {
            int k = g * 32 + lane;
            e[g] = -INFINITY;
            if (active && k < nk) {
                int j = s_idx[k];
                if (adjrow[j] > 0) e[g] = s_e[k];
            }
        }
        float cm = e[0];
        #pragma unroll
        for (int g = 1; g < GROUPS; ++g) cm = fmaxf(cm, e[g]);
        for (int d = 16; d; d >>= 1) cm = fmaxf(cm, __shfl_xor_sync(0xffffffffu, cm, d));
        if (cm > m) {
            if (m > -INFINITY) {
                float sc = __expf(m - cm);
                acc.x *= sc; acc.y *= sc; acc.z *= sc; acc.w *= sc;
                denom *= sc;
            }
            m = cm;
        }
        if (m > -INFINITY) {
            float wgt[GROUPS];
            float ls = 0.f;
            #pragma unroll
            for (int g = 0; g < GROUPS; ++g) {
                wgt[g] = __expf(e[g] - m);   // -inf -> 0, no branch
                ls += wgt[g];
            }
            for (int d = 16; d; d >>= 1) ls += __shfl_xor_sync(0xffffffffu, ls, d);
            denom += ls;
            #pragma unroll
            for (int g = 0; g < GROUPS; ++g) {
                unsigned msk = __ballot_sync(0xffffffffu, wgt[g] != 0.f);
                while (msk) {
                    int b = __ffs(msk) - 1;
                    msk &= msk - 1;
                    float wb = __shfl_sync(0xffffffffu, wgt[g], b);
                    float4 hv = hwC4[(size_t)(base + g * 32 + b) * (NOUT / 4) + lane];
                    acc.x = fmaf(wb, hv.x, acc.x);
                    acc.y = fmaf(wb, hv.y, acc.y);
                    acc.z = fmaf(wb, hv.z, acc.z);
                    acc.w = fmaf(wb, hv.w, acc.w);
                }
            }
        }
        __syncthreads();
    }

    if (!active) return;
    bool flag = !(m >= Mthr);
    if (flag && lane == 0) { g_flags[row] = 1; atomicAdd(&g_flag_count, 1); }
    float inv = 1.f / denom;
    float4 o;
    o.x = flag ? 0.f : acc.x * inv;
    o.y = flag ? 0.f : acc.y * inv;
    o.z = flag ? 0.f : acc.z * inv;
    o.w = flag ? 0.f : acc.w * inv;
    ((float4*)out)[(size_t)row * (NOUT / 4) + lane] = o;
}

// k6: exact fallback for flagged rows; whole grid exits on one load when
// no rows were flagged (the statistically-certain case).
__global__ void k6_fallback(const int* __restrict__ adj, const float* __restrict__ h,
                            const float* __restrict__ w, float* __restrict__ out, int N) {
    if (g_flag_count == 0) return;
    int t = threadIdx.x;  // 128
    __shared__ float s_red[128];
    __shared__ int   s_list[512];
    __shared__ float s_wl[512];
    __shared__ int   s_cnt;
    __shared__ float s_h[NIN];

    for (int row = blockIdx.x; row < N; row += gridDim.x) {
        if (!g_flags[row]) continue;
        const int* adjrow = adj + (size_t)row * N;

        float lm = -INFINITY;
        for (int j = t; j < N; j += 128)
            if (adjrow[j] > 0) lm = fmaxf(lm, g_hw2[j]);
        s_red[t] = lm;
        __syncthreads();
        for (int s = 64; s; s >>= 1) {
            if (t < s) s_red[t] = fmaxf(s_red[t], s_red[t + s]);
            __syncthreads();
        }
        float m = s_red[0];
        __syncthreads();
        bool uni = !(m > -INFINITY);  // fully masked row -> uniform softmax

        float acc = 0.f, denom = 0.f;
        for (int cb = 0; cb < N; cb += 512) {
            if (t == 0) s_cnt = 0;
            __syncthreads();
            int ce = min(cb + 512, N);
            for (int j = cb + t; j < ce; j += 128) {
                bool act = uni ? true : (adjrow[j] > 0 && g_hw2[j] >= m - KEEP);
                if (act) {
                    int p = atomicAdd(&s_cnt, 1);
                    s_list[p] = j;
                    s_wl[p]   = uni ? 1.f : expf(g_hw2[j] - m);
                }
            }
            __syncthreads();
            int L = s_cnt;
            for (int l = 0; l < L; ++l) {
                int j = s_list[l];
                float wl = s_wl[l];
                s_h[t]       = h[(size_t)j * NIN + t];
                s_h[t + 128] = h[(size_t)j * NIN + t + 128];
                __syncthreads();
                float dot = 0.f;
                #pragma unroll 8
                for (int kk = 0; kk < NIN; ++kk)
                    dot = fmaf(s_h[kk], w[kk * NOUT + t], dot);
                acc = fmaf(wl, dot, acc);
                denom += wl;
                __syncthreads();
            }
            __syncthreads();
        }
        out[(size_t)row * NOUT + t] = acc / denom;
        __syncthreads();
    }
}

extern "C" void kernel_launch(void* const* d_in, const int* in_sizes, int n_in,
                              void* d_out, int out_size) {
    const float* h   = (const float*)d_in[0];
    const int*   adj = (const int*)d_in[1];
    const float* w   = (const float*)d_in[2];
    const float* v   = (const float*)d_in[3];
    float* out = (float*)d_out;

    int nout = in_sizes[3] / 2;        // 128
    int nin  = in_sizes[2] / nout;     // 256
    int N    = in_sizes[0] / nin;      // 8192
    (void)nout; (void)nin; (void)n_in; (void)out_size;

    k1_wv2<<<1, NIN>>>(w, v);
    k2_hw2<<<(N + 15) / 16, 512>>>(h, N);
    k3_candidates<<<1, 1024>>>(N);
    k4_hwC<<<128, 1024>>>(h, w);
    k5_main<<<(N + 7) / 8, 256>>>(adj, out, N);
    k6_fallback<<<256, 128>>>(adj, h, w, out, N);
}

// round 9
// speedup vs baseline: 14.0401x; 1.4718x over previous
#include <cuda_runtime.h>
#include <math.h>
#include <float.h>

// Problem-fixed dims: N=8192, nin=256, nout=128
#define MAXN 8192
#define NIN  256
#define NOUT 128
#define NB   148      // persistent grid: 1 block/SM, co-resident (GB300 = 152 SMs)
#define NT   1024

// Candidate window below global max M of hw2 (std ~181, Gumbel scale ~43).
// cnt ~ e^{160/43} ~ 43. A row falls back only if it misses ALL ~17 nodes
// within 120 of M: P ~ 0.5^17 * 8192 ~ 0.06 rows expected. Fallback phase
// recomputes flagged rows exactly, so this is purely a speed knob.
// Dropped softmax terms have weight <= e^-40 ~ 4e-18 (exact 0 in fp32 ref).
#define DELTA_CAND 160.0f
#define KEEP        40.0f

// -------- device scratch (no allocations allowed) --------
__device__ float    g_hw2[MAXN];
__device__ float    g_Mthr;
__device__ int      g_cand_count;
__device__ int      g_flag_count;
__device__ int      g_cand_idx[MAXN];
__device__ float    g_cand_e[MAXN];
__device__ float    g_hwC[(size_t)MAXN * NOUT];
__device__ int      g_flag_list[MAXN];
__device__ unsigned g_bar_cnt;   // zero-init; reset by last block each launch
__device__ unsigned g_done_cnt;

// Software global barrier: thread 0 arrives + spins, block follows.
__device__ __forceinline__ void gbar(unsigned target) {
    __syncthreads();
    if (threadIdx.x == 0) {
        __threadfence();
        atomicAdd(&g_bar_cnt, 1u);
        while (*(volatile unsigned*)&g_bar_cnt < target) { }
        __threadfence();
    }
    __syncthreads();
}

__global__ void __launch_bounds__(NT, 1)
gat_persistent(const float* __restrict__ h, const int* __restrict__ adj,
               const float* __restrict__ w, const float* __restrict__ v,
               float* __restrict__ out, int N)
{
    __shared__ __align__(16) float s_wv2[NIN];
    __shared__ float s_red[NT];
    __shared__ int   s_wsum[32], s_woff[32];
    __shared__ __align__(16) float s_h[NIN];
    __shared__ float s_part[8][NOUT];
    __shared__ float s_acc[NOUT];
    __shared__ int   s_list[512];
    __shared__ float s_wl[512];
    __shared__ int   s_cnt;

    const int t    = threadIdx.x;
    const int lane = t & 31;
    const int blk  = blockIdx.x;

    // ---- Phase A: wv2 = w @ v2, redundant per block (no barrier needed) ----
    {
        int k = t >> 2, part = t & 3;           // 256 k's x 4 partials
        const float4* wr = (const float4*)(w + (size_t)k * NOUT + part * 32);
        const float4* v2 = (const float4*)(v + NOUT + part * 32);
        float a0 = 0.f, a1 = 0.f;
        #pragma unroll
        for (int q = 0; q < 8; ++q) {
            float4 wa = wr[q], va = v2[q];
            a0 = fmaf(wa.x, va.x, a0); a1 = fmaf(wa.y, va.y, a1);
            a0 = fmaf(wa.z, va.z, a0); a1 = fmaf(wa.w, va.w, a1);
        }
        float p = a0 + a1;
        p += __shfl_xor_sync(0xffffffffu, p, 1);
        p += __shfl_xor_sync(0xffffffffu, p, 2);
        if (part == 0) s_wv2[k] = p;
    }
    __syncthreads();

    // ---- Phase B: hw2[row] = h[row,:] . wv2 (warp per row) ----
    {
        const float4* wv = (const float4*)s_wv2;
        float4 wa = wv[lane], wb = wv[lane + 32];
        for (int row = blk * 32 + (t >> 5); row < N; row += NB * 32) {
            const float4* hr = (const float4*)(h + (size_t)row * NIN);
            float4 a = hr[lane], b = hr[lane + 32];
            float acc = 0.f;
            acc = fmaf(a.x, wa.x, acc); acc = fmaf(a.y, wa.y, acc);
            acc = fmaf(a.z, wa.z, acc); acc = fmaf(a.w, wa.w, acc);
            acc = fmaf(b.x, wb.x, acc); acc = fmaf(b.y, wb.y, acc);
            acc = fmaf(b.z, wb.z, acc); acc = fmaf(b.w, wb.w, acc);
            for (int d = 16; d; d >>= 1) acc += __shfl_down_sync(0xffffffffu, acc, d);
            if (lane == 0) g_hw2[row] = acc;
        }
    }
    gbar(NB * 1);

    // ---- Phase C: block 0 only — global max + deterministic compaction ----
    if (blk == 0) {
        int wid = t >> 5;
        float lm = -INFINITY;
        for (int j = t; j < N; j += NT) lm = fmaxf(lm, g_hw2[j]);
        s_red[t] = lm;
        __syncthreads();
        for (int s = 512; s; s >>= 1) {
            if (t < s) s_red[t] = fmaxf(s_red[t], s_red[t + s]);
            __syncthreads();
        }
        float M = s_red[0];
        __syncthreads();
        float thr = M - DELTA_CAND;
        if (t == 0) { g_Mthr = M - (DELTA_CAND - KEEP); g_flag_count = 0; }

        int per = (N + NT - 1) / NT;  // 8
        int j0 = t * per;
        int c = 0;
        for (int r = 0; r < per; ++r) {
            int j = j0 + r;
            if (j < N && g_hw2[j] >= thr) c++;
        }
        int inc = c;
        for (int d = 1; d < 32; d <<= 1) {
            int vv = __shfl_up_sync(0xffffffffu, inc, d);
            if (lane >= d) inc += vv;
        }
        if (lane == 31) s_wsum[wid] = inc;
        __syncthreads();
        if (wid == 0) {
            int vv = s_wsum[lane];
            int winc = vv;
            for (int d = 1; d < 32; d <<= 1) {
                int u = __shfl_up_sync(0xffffffffu, winc, d);
                if (lane >= d) winc += u;
            }
            s_woff[lane] = winc - vv;
            if (lane == 31) g_cand_count = winc;
        }
        __syncthreads();
        int pos = s_woff[wid] + (inc - c);
        for (int r = 0; r < per; ++r) {
            int j = j0 + r;
            if (j < N && g_hw2[j] >= thr) {
                g_cand_idx[pos] = j;
                g_cand_e[pos]   = g_hw2[j];
                pos++;
            }
        }
    }
    gbar(NB * 2);

    // ---- Phase D: hwC[c,:] = h[cand[c],:] @ w  (8 K-groups x 128 cols) ----
    const int cnt = g_cand_count;
    {
        int col = t & 127, kg = t >> 7;
        for (int c = blk; c < cnt; c += NB) {
            if (t < NIN / 4)
                ((float4*)s_h)[t] = ((const float4*)(h + (size_t)g_cand_idx[c] * NIN))[t];
            __syncthreads();
            const float* wc = w + (size_t)(kg * 32) * NOUT + col;
            float a0 = 0.f, a1 = 0.f, a2 = 0.f, a3 = 0.f;
            #pragma unroll
            for (int b = 0; b < 2; ++b) {
                float wv[16];
                #pragma unroll
                for (int u = 0; u < 16; ++u)
                    wv[u] = wc[(size_t)(b * 16 + u) * NOUT];
                #pragma unroll
                for (int u = 0; u < 16; u += 4) {
                    a0 = fmaf(s_h[kg * 32 + b * 16 + u],     wv[u],     a0);
                    a1 = fmaf(s_h[kg * 32 + b * 16 + u + 1], wv[u + 1], a1);
                    a2 = fmaf(s_h[kg * 32 + b * 16 + u + 2], wv[u + 2], a2);
                    a3 = fmaf(s_h[kg * 32 + b * 16 + u + 3], wv[u + 3], a3);
                }
            }
            s_part[kg][col] = (a0 + a1) + (a2 + a3);
            __syncthreads();
            if (t < NOUT) {
                float s = 0.f;
                #pragma unroll
                for (int g = 0; g < 8; ++g) s += s_part[g][t];
                g_hwC[(size_t)c * NOUT + t] = s;
            }
            __syncthreads();
        }
    }
    gbar(NB * 3);

    // ---- Phase E: main pass (warp per row, fully independent warps) ----
    {
        const float Mthr = g_Mthr;
        const float4* hwC4 = (const float4*)g_hwC;
        for (int row = blk * 32 + (t >> 5); row < N; row += NB * 32) {
            const int* adjrow = adj + (size_t)row * N;
            float m = -INFINITY, denom = 0.f;
            float4 acc = make_float4(0.f, 0.f, 0.f, 0.f);

            for (int base = 0; base < cnt; base += 256) {
                int nk = min(256, cnt - base);
                float e[8];
                #pragma unroll
                for (int g = 0; g < 8; ++g) {
                    int k = g * 32 + lane;
                    e[g] = -INFINITY;
                    if (k < nk) {
                        int j = g_cand_idx[base + k];
                        if (adjrow[j] > 0) e[g] = g_cand_e[base + k];
                    }
                }
                float cm = e[0];
                #pragma unroll
                for (int g = 1; g < 8; ++g) cm = fmaxf(cm, e[g]);
                for (int d = 16; d; d >>= 1)
                    cm = fmaxf(cm, __shfl_xor_sync(0xffffffffu, cm, d));
                if (cm > m) {
                    if (m > -INFINITY) {
                        float sc = __expf(m - cm);
                        acc.x *= sc; acc.y *= sc; acc.z *= sc; acc.w *= sc;
                        denom *= sc;
                    }
                    m = cm;
                }
                if (m > -INFINITY) {
                    float wgt[8];
                    float ls = 0.f;
                    #pragma unroll
                    for (int g = 0; g < 8; ++g) {
                        wgt[g] = __expf(e[g] - m);   // -inf -> 0, no branch
                        ls += wgt[g];
                    }
                    for (int d = 16; d; d >>= 1)
                        ls += __shfl_xor_sync(0xffffffffu, ls, d);
                    denom += ls;
                    #pragma unroll
                    for (int g = 0; g < 8; ++g) {
                        unsigned msk = __ballot_sync(0xffffffffu, wgt[g] != 0.f);
                        while (msk) {
                            int b = __ffs(msk) - 1;
                            msk &= msk - 1;
                            float wb = __shfl_sync(0xffffffffu, wgt[g], b);
                            float4 hv = hwC4[(size_t)(base + g * 32 + b) * (NOUT / 4) + lane];
                            acc.x = fmaf(wb, hv.x, acc.x);
                            acc.y = fmaf(wb, hv.y, acc.y);
                            acc.z = fmaf(wb, hv.z, acc.z);
                            acc.w = fmaf(wb, hv.w, acc.w);
                        }
                    }
                }
            }

            bool flag = !(m >= Mthr);
            if (flag && lane == 0) {
                int p = atomicAdd(&g_flag_count, 1);
                g_flag_list[p] = row;
            }
            float inv = flag ? 0.f : (1.f / denom);
            float4 o = make_float4(acc.x * inv, acc.y * inv, acc.z * inv, acc.w * inv);
            ((float4*)out)[(size_t)row * (NOUT / 4) + lane] = o;
        }
    }
    gbar(NB * 4);

    // ---- Phase F: exact fallback for flagged rows (statistically ~0) ----
    {
        int fc = g_flag_count;
        for (int f = blk; f < fc; f += NB) {
            int row = g_flag_list[f];
            const int* adjrow = adj + (size_t)row * N;

            float lm = -INFINITY;
            for (int j = t; j < N; j += NT)
                if (adjrow[j] > 0) lm = fmaxf(lm, g_hw2[j]);
            s_red[t] = lm;
            __syncthreads();
            for (int s = 512; s; s >>= 1) {
                if (t < s) s_red[t] = fmaxf(s_red[t], s_red[t + s]);
                __syncthreads();
            }
            float m = s_red[0];
            __syncthreads();
            bool uni = !(m > -INFINITY);  // fully masked row -> uniform softmax

            if (t < NOUT) s_acc[t] = 0.f;
            float denom = 0.f;
            int col = t & 127, kg = t >> 7;
            for (int cb = 0; cb < N; cb += 512) {
                if (t == 0) s_cnt = 0;
                __syncthreads();
                int ce = min(cb + 512, N);
                for (int j = cb + t; j < ce; j += NT) {
                    bool act = uni ? true : (adjrow[j] > 0 && g_hw2[j] >= m - KEEP);
                    if (act) {
                        int p = atomicAdd(&s_cnt, 1);
                        s_list[p] = j;
                        s_wl[p]   = uni ? 1.f : expf(g_hw2[j] - m);
                    }
                }
                __syncthreads();
                int L = s_cnt;
                for (int l = 0; l < L; ++l) {
                    int j = s_list[l];
                    float wl = s_wl[l];
                    if (t < NIN / 4)
                        ((float4*)s_h)[t] = ((const float4*)(h + (size_t)j * NIN))[t];
                    __syncthreads();
                    const float* wc = w + (size_t)(kg * 32) * NOUT + col;
                    float a0 = 0.f, a1 = 0.f, a2 = 0.f, a3 = 0.f;
                    #pragma unroll
                    for (int b = 0; b < 2; ++b) {
                        float wv[16];
                        #pragma unroll
                        for (int u = 0; u < 16; ++u)
                            wv[u] = wc[(size_t)(b * 16 + u) * NOUT];
                        #pragma unroll
                        for (int u = 0; u < 16; u += 4) {
                            a0 = fmaf(s_h[kg * 32 + b * 16 + u],     wv[u],     a0);
                            a1 = fmaf(s_h[kg * 32 + b * 16 + u + 1], wv[u + 1], a1);
                            a2 = fmaf(s_h[kg * 32 + b * 16 + u + 2], wv[u + 2], a2);
                            a3 = fmaf(s_h[kg * 32 + b * 16 + u + 3], wv[u + 3], a3);
                        }
                    }
                    s_part[kg][col] = (a0 + a1) + (a2 + a3);
                    __syncthreads();
                    if (t < NOUT) {
                        float s = 0.f;
                        #pragma unroll
                        for (int g = 0; g < 8; ++g) s += s_part[g][t];
                        s_acc[t] += wl * s;
                    }
                    denom += wl;
                    __syncthreads();
                }
                __syncthreads();
            }
            if (t < NOUT) out[(size_t)row * NOUT + t] = s_acc[t] / denom;
            __syncthreads();
        }
    }

    // ---- Epilogue: last block resets barrier counters for next replay ----
    __syncthreads();
    if (t == 0) {
        unsigned r = atomicAdd(&g_done_cnt, 1u);
        if (r == NB - 1) {
            *(volatile unsigned*)&g_done_cnt = 0;
            *(volatile unsigned*)&g_bar_cnt  = 0;
            __threadfence();
        }
    }
}

extern "C" void kernel_launch(void* const* d_in, const int* in_sizes, int n_in,
                              void* d_out, int out_size) {
    const float* h   = (const float*)d_in[0];
    const int*   adj = (const int*)d_in[1];
    const float* w   = (const float*)d_in[2];
    const float* v   = (const float*)d_in[3];
    float* out = (float*)d_out;

    int nout = in_sizes[3] / 2;        // 128
    int nin  = in_sizes[2] / nout;     // 256
    int N    = in_sizes[0] / nin;      // 8192
    (void)nout; (void)nin; (void)n_in; (void)out_size;

    gat_persistent<<<NB, NT>>>(h, adj, w, v, out, N);
}

// round 10
// speedup vs baseline: 14.6012x; 1.0400x over previous
#include <cuda_runtime.h>
#include <math.h>
#include <float.h>

// Problem-fixed dims: N=8192, nin=256, nout=128
#define MAXN 8192
#define NIN  256
#define NOUT 128
#define NB   148      // persistent grid: 1 block/SM, co-resident
#define NT   1024

// Candidate window below global max M of hw2 (std ~181, Gumbel scale ~43).
// cnt ~ e^{160/43} ~ 43. A row falls back only if it misses ALL ~17 nodes
// within 120 of M: P ~ 0.5^17 * 8192 ~ 0.06 rows expected. Fallback phase
// recomputes flagged rows exactly, so this is purely a speed knob.
#define DELTA_CAND 160.0f
#define KEEP        40.0f

#define CAP        1024   // smem candidate capacity (cnt>CAP -> full fallback)
#define CAP_STAGE  192    // candidates staged in dynamic smem for phase E

// -------- device scratch (no allocations allowed) --------
__device__ float    g_hw2[MAXN];
__device__ int      g_flag_count;
__device__ float    g_hwC[(size_t)CAP * NOUT];
__device__ int      g_flag_list[MAXN];
__device__ unsigned g_bar_cnt;   // zero-init; reset by last block each launch
__device__ unsigned g_done_cnt;

// Software global barrier: thread 0 arrives + spins, block follows.
__device__ __forceinline__ void gbar(unsigned target) {
    __syncthreads();
    if (threadIdx.x == 0) {
        __threadfence();
        atomicAdd(&g_bar_cnt, 1u);
        while (*(volatile unsigned*)&g_bar_cnt < target) { }
        __threadfence();
    }
    __syncthreads();
}

__global__ void __launch_bounds__(NT, 1)
gat_persistent(const float* __restrict__ h, const int* __restrict__ adj,
               const float* __restrict__ w, const float* __restrict__ v,
               float* __restrict__ out, int N)
{
    extern __shared__ __align__(16) float s_hwC[];   // CAP_STAGE * NOUT floats

    __shared__ __align__(16) float s_wv2[NIN];
    __shared__ float s_red[NT];
    __shared__ int   s_wsum[32], s_woff[32];
    __shared__ int   s_idx[CAP];
    __shared__ float s_e[CAP];
    __shared__ __align__(16) float s_h[NIN];
    __shared__ float s_part[8][NOUT];
    __shared__ float s_acc[NOUT];
    __shared__ int   s_list[512];
    __shared__ float s_wl[512];
    __shared__ int   s_cnt;

    const int t    = threadIdx.x;
    const int lane = t & 31;
    const int wid  = t >> 5;
    const int blk  = blockIdx.x;

    // ---- Phase A: wv2 = w @ v2, redundant per block ----
    {
        int k = t >> 2, part = t & 3;           // 256 k's x 4 partials
        const float4* wr = (const float4*)(w + (size_t)k * NOUT + part * 32);
        const float4* v2 = (const float4*)(v + NOUT + part * 32);
        float a0 = 0.f, a1 = 0.f;
        #pragma unroll
        for (int q = 0; q < 8; ++q) {
            float4 wa = wr[q], va = v2[q];
            a0 = fmaf(wa.x, va.x, a0); a1 = fmaf(wa.y, va.y, a1);
            a0 = fmaf(wa.z, va.z, a0); a1 = fmaf(wa.w, va.w, a1);
        }
        float p = a0 + a1;
        p += __shfl_xor_sync(0xffffffffu, p, 1);
        p += __shfl_xor_sync(0xffffffffu, p, 2);
        if (part == 0) s_wv2[k] = p;
    }
    __syncthreads();

    // ---- Phase B: hw2[row] = h[row,:] . wv2 (warp per row) ----
    {
        const float4* wv = (const float4*)s_wv2;
        float4 wa = wv[lane], wb = wv[lane + 32];
        for (int row = blk * 32 + wid; row < N; row += NB * 32) {
            const float4* hr = (const float4*)(h + (size_t)row * NIN);
            float4 a = hr[lane], b = hr[lane + 32];
            float acc = 0.f;
            acc = fmaf(a.x, wa.x, acc); acc = fmaf(a.y, wa.y, acc);
            acc = fmaf(a.z, wa.z, acc); acc = fmaf(a.w, wa.w, acc);
            acc = fmaf(b.x, wb.x, acc); acc = fmaf(b.y, wb.y, acc);
            acc = fmaf(b.z, wb.z, acc); acc = fmaf(b.w, wb.w, acc);
            for (int d = 16; d; d >>= 1) acc += __shfl_down_sync(0xffffffffu, acc, d);
            if (lane == 0) g_hw2[row] = acc;
        }
    }
    gbar(NB * 1);

    // ---- Phase C (redundant per block): global max + compaction into smem.
    // Deterministic and identical across blocks; no single-block stall. ----
    float Mthr;
    int   cnt;
    {
        float lm = -INFINITY;
        int per = N / NT;  // 8, contiguous per thread
        int j0 = t * per;
        #pragma unroll
        for (int r = 0; r < 8; ++r) lm = fmaxf(lm, g_hw2[j0 + r]);
        s_red[t] = lm;
        __syncthreads();
        for (int s = 512; s; s >>= 1) {
            if (t < s) s_red[t] = fmaxf(s_red[t], s_red[t + s]);
            __syncthreads();
        }
        float M = s_red[0];
        __syncthreads();
        float thr = M - DELTA_CAND;
        Mthr = M - (DELTA_CAND - KEEP);
        if (t == 0) g_flag_count = 0;   // all blocks write 0: benign

        int c = 0;
        #pragma unroll
        for (int r = 0; r < 8; ++r)
            if (g_hw2[j0 + r] >= thr) c++;
        int inc = c;
        for (int d = 1; d < 32; d <<= 1) {
            int vv = __shfl_up_sync(0xffffffffu, inc, d);
            if (lane >= d) inc += vv;
        }
        if (lane == 31) s_wsum[wid] = inc;
        __syncthreads();
        if (wid == 0) {
            int vv = s_wsum[lane];
            int winc = vv;
            for (int d = 1; d < 32; d <<= 1) {
                int u = __shfl_up_sync(0xffffffffu, winc, d);
                if (lane >= d) winc += u;
            }
            s_woff[lane] = winc - vv;
            if (lane == 31) s_cnt = winc;
        }
        __syncthreads();
        cnt = s_cnt;
        if (cnt <= CAP) {
            int pos = s_woff[wid] + (inc - c);
            #pragma unroll
            for (int r = 0; r < 8; ++r) {
                int j = j0 + r;
                if (g_hw2[j] >= thr) {
                    s_idx[pos] = j;
                    s_e[pos]   = g_hw2[j];
                    pos++;
                }
            }
        } else {
            cnt = 0;                    // overflow: force full exact fallback
            Mthr = INFINITY;
        }
        __syncthreads();
    }

    // ---- Phase D: hwC[c,:] = h[cand[c],:] @ w  (8 K-groups x 128 cols) ----
    {
        int col = t & 127, kg = t >> 7;
        for (int c = blk; c < cnt; c += NB) {
            if (t < NIN / 4)
                ((float4*)s_h)[t] = ((const float4*)(h + (size_t)s_idx[c] * NIN))[t];
            __syncthreads();
            const float* wc = w + (size_t)(kg * 32) * NOUT + col;
            float a0 = 0.f, a1 = 0.f, a2 = 0.f, a3 = 0.f;
            #pragma unroll
            for (int b = 0; b < 2; ++b) {
                float wv[16];
                #pragma unroll
                for (int u = 0; u < 16; ++u)
                    wv[u] = wc[(size_t)(b * 16 + u) * NOUT];
                #pragma unroll
                for (int u = 0; u < 16; u += 4) {
                    a0 = fmaf(s_h[kg * 32 + b * 16 + u],     wv[u],     a0);
                    a1 = fmaf(s_h[kg * 32 + b * 16 + u + 1], wv[u + 1], a1);
                    a2 = fmaf(s_h[kg * 32 + b * 16 + u + 2], wv[u + 2], a2);
                    a3 = fmaf(s_h[kg * 32 + b * 16 + u + 3], wv[u + 3], a3);
                }
            }
            s_part[kg][col] = (a0 + a1) + (a2 + a3);
            __syncthreads();
            if (t < NOUT) {
                float s = 0.f;
                #pragma unroll
                for (int g = 0; g < 8; ++g) s += s_part[g][t];
                g_hwC[(size_t)c * NOUT + t] = s;
            }
            __syncthreads();
        }
    }
    gbar(NB * 2);

    // ---- Stage hwC into dynamic smem (LDS accumulate instead of L2) ----
    const int nstage = min(cnt, CAP_STAGE);
    for (int i = t; i < nstage * (NOUT / 4); i += NT)
        ((float4*)s_hwC)[i] = ((const float4*)g_hwC)[i];
    __syncthreads();

    // ---- Phase E: main pass (warp per row, fully independent warps) ----
    {
        const float4* hwC4 = (const float4*)g_hwC;
        for (int row = blk * 32 + wid; row < N; row += NB * 32) {
            const int* adjrow = adj + (size_t)row * N;
            float m = -INFINITY, denom = 0.f;
            float4 acc = make_float4(0.f, 0.f, 0.f, 0.f);

            for (int base = 0; base < cnt; base += 256) {
                int nk = min(256, cnt - base);
                float e[8];
                #pragma unroll
                for (int g = 0; g < 8; ++g) {
                    int k = g * 32 + lane;
                    e[g] = -INFINITY;
                    if (k < nk) {
                        int j = s_idx[base + k];
                        if (adjrow[j] > 0) e[g] = s_e[base + k];
                    }
                }
                float cm = e[0];
                #pragma unroll
                for (int g = 1; g < 8; ++g) cm = fmaxf(cm, e[g]);
                for (int d = 16; d; d >>= 1)
                    cm = fmaxf(cm, __shfl_xor_sync(0xffffffffu, cm, d));
                if (cm > m) {
                    if (m > -INFINITY) {
                        float sc = __expf(m - cm);
                        acc.x *= sc; acc.y *= sc; acc.z *= sc; acc.w *= sc;
                        denom *= sc;
                    }
                    m = cm;
                }
                if (m > -INFINITY) {
                    float wgt[8];
                    float ls = 0.f;
                    #pragma unroll
                    for (int g = 0; g < 8; ++g) {
                        wgt[g] = __expf(e[g] - m);   // -inf -> 0, no branch
                        ls += wgt[g];
                    }
                    for (int d = 16; d; d >>= 1)
                        ls += __shfl_xor_sync(0xffffffffu, ls, d);
                    denom += ls;
                    #pragma unroll
                    for (int g = 0; g < 8; ++g) {
                        unsigned msk = __ballot_sync(0xffffffffu, wgt[g] != 0.f);
                        while (msk) {
                            int b = __ffs(msk) - 1;
                            msk &= msk - 1;
                            float wb = __shfl_sync(0xffffffffu, wgt[g], b);
                            int c = base + g * 32 + b;
                            float4 hv = (c < nstage)
                                ? ((const float4*)s_hwC)[c * (NOUT / 4) + lane]
                                : hwC4[(size_t)c * (NOUT / 4) + lane];
                            acc.x = fmaf(wb, hv.x, acc.x);
                            acc.y = fmaf(wb, hv.y, acc.y);
                            acc.z = fmaf(wb, hv.z, acc.z);
                            acc.w = fmaf(wb, hv.w, acc.w);
                        }
                    }
                }
            }

            bool flag = !(m >= Mthr);
            if (flag && lane == 0) {
                int p = atomicAdd(&g_flag_count, 1);
                g_flag_list[p] = row;
            }
            float inv = flag ? 0.f : (1.f / denom);
            float4 o = make_float4(acc.x * inv, acc.y * inv, acc.z * inv, acc.w * inv);
            ((float4*)out)[(size_t)row * (NOUT / 4) + lane] = o;
        }
    }
    gbar(NB * 3);

    // ---- Phase F: exact fallback for flagged rows (statistically ~0) ----
    {
        int fc = g_flag_count;
        for (int f = blk; f < fc; f += NB) {
            int row = g_flag_list[f];
            const int* adjrow = adj + (size_t)row * N;

            float lm = -INFINITY;
            for (int j = t; j < N; j += NT)
                if (adjrow[j] > 0) lm = fmaxf(lm, g_hw2[j]);
            s_red[t] = lm;
            __syncthreads();
            for (int s = 512; s; s >>= 1) {
                if (t < s) s_red[t] = fmaxf(s_red[t], s_red[t + s]);
                __syncthreads();
            }
            float m = s_red[0];
            __syncthreads();
            bool uni = !(m > -INFINITY);  // fully masked row -> uniform softmax

            if (t < NOUT) s_acc[t] = 0.f;
            float denom = 0.f;
            int col = t & 127, kg = t >> 7;
            for (int cb = 0; cb < N; cb += 512) {
                if (t == 0) s_cnt = 0;
                __syncthreads();
                int ce = min(cb + 512, N);
                for (int j = cb + t; j < ce; j += NT) {
                    bool act = uni ? true : (adjrow[j] > 0 && g_hw2[j] >= m - KEEP);
                    if (act) {
                        int p = atomicAdd(&s_cnt, 1);
                        s_list[p] = j;
                        s_wl[p]   = uni ? 1.f : expf(g_hw2[j] - m);
                    }
                }
                __syncthreads();
                int L = s_cnt;
                for (int l = 0; l < L; ++l) {
                    int j = s_list[l];
                    float wl = s_wl[l];
                    if (t < NIN / 4)
                        ((float4*)s_h)[t] = ((const float4*)(h + (size_t)j * NIN))[t];
                    __syncthreads();
                    const float* wc = w + (size_t)(kg * 32) * NOUT + col;
                    float a0 = 0.f, a1 = 0.f, a2 = 0.f, a3 = 0.f;
                    #pragma unroll
                    for (int b = 0; b < 2; ++b) {
                        float wv[16];
                        #pragma unroll
                        for (int u = 0; u < 16; ++u)
                            wv[u] = wc[(size_t)(b * 16 + u) * NOUT];
                        #pragma unroll
                        for (int u = 0; u < 16; u += 4) {
                            a0 = fmaf(s_h[kg * 32 + b * 16 + u],     wv[u],     a0);
                            a1 = fmaf(s_h[kg * 32 + b * 16 + u + 1], wv[u + 1], a1);
                            a2 = fmaf(s_h[kg * 32 + b * 16 + u + 2], wv[u + 2], a2);
                            a3 = fmaf(s_h[kg * 32 + b * 16 + u + 3], wv[u + 3], a3);
                        }
                    }
                    s_part[kg][col] = (a0 + a1) + (a2 + a3);
                    __syncthreads();
                    if (t < NOUT) {
                        float s = 0.f;
                        #pragma unroll
                        for (int g = 0; g < 8; ++g) s += s_part[g][t];
                        s_acc[t] += wl * s;
                    }
                    denom += wl;
                    __syncthreads();
                }
                __syncthreads();
            }
            if (t < NOUT) out[(size_t)row * NOUT + t] = s_acc[t] / denom;
            __syncthreads();
        }
    }

    // ---- Epilogue: last block resets barrier counters for next replay ----
    __syncthreads();
    if (t == 0) {
        unsigned r = atomicAdd(&g_done_cnt, 1u);
        if (r == NB - 1) {
            *(volatile unsigned*)&g_done_cnt = 0;
            *(volatile unsigned*)&g_bar_cnt  = 0;
            __threadfence();
        }
    }
}

extern "C" void kernel_launch(void* const* d_in, const int* in_sizes, int n_in,
                              void* d_out, int out_size) {
    const float* h   = (const float*)d_in[0];
    const int*   adj = (const int*)d_in[1];
    const float* w   = (const float*)d_in[2];
    const float* v   = (const float*)d_in[3];
    float* out = (float*)d_out;

    int nout = in_sizes[3] / 2;        // 128
    int nin  = in_sizes[2] / nout;     // 256
    int N    = in_sizes[0] / nin;      // 8192
    (void)nout; (void)nin; (void)n_in; (void)out_size;

    const int dyn_smem = CAP_STAGE * NOUT * sizeof(float);  // 96 KB
    cudaFuncSetAttribute(gat_persistent,
                         cudaFuncAttributeMaxDynamicSharedMemorySize, dyn_smem);
    gat_persistent<<<NB, NT, dyn_smem>>>(h, adj, w, v, out, N);
}

// round 11
// speedup vs baseline: 16.5106x; 1.1308x over previous
#include <cuda_runtime.h>
#include <math.h>
#include <float.h>

// Problem-fixed dims: N=8192, nin=256, nout=128
#define MAXN 8192
#define NIN  256
#define NOUT 128
#define NB   148      // persistent grid: 1 block/SM, co-resident
#define NT   1024

// Candidate window below global max M of hw2 (std ~181, Gumbel scale ~43).
// cnt ~ e^{160/43} ~ 43. A row is flagged only if it misses ALL ~17 nodes
// within 120 of M: P ~ 0.5^17 * 8192 ~ 0.06 rows expected; flagged rows are
// recomputed exactly in phase F. Dropped terms weigh <= e^-40 ~ 4e-18.
#define DELTA_CAND 160.0f
#define KEEP        40.0f

#define CAP        256    // candidate capacity (cnt>CAP -> full exact fallback)
#define CAP_STAGE  128    // candidates staged in dynamic smem for accumulate

// -------- device scratch (no allocations allowed) --------
__device__ float    g_hw2[MAXN];
__device__ unsigned g_M_key;          // ordered-uint encoding of global max
__device__ int      g_flag_count;
__device__ float    g_hwC[(size_t)CAP * NOUT];
__device__ int      g_flag_list[MAXN];
__device__ unsigned g_bar_cnt;        // zero-init; reset by last block
__device__ unsigned g_done_cnt;

__device__ __forceinline__ unsigned fkey(float f) {
    unsigned b = __float_as_uint(f);
    return b ^ ((b >> 31) ? 0xFFFFFFFFu : 0x80000000u);
}
__device__ __forceinline__ float fkey_inv(unsigned k) {
    unsigned b = (k & 0x80000000u) ? (k ^ 0x80000000u) : ~k;
    return __uint_as_float(b);
}

// Software global barrier: thread 0 arrives + spins, block follows.
__device__ __forceinline__ void gbar(unsigned target) {
    __syncthreads();
    if (threadIdx.x == 0) {
        __threadfence();
        atomicAdd(&g_bar_cnt, 1u);
        while (*(volatile unsigned*)&g_bar_cnt < target) { }
        __threadfence();
    }
    __syncthreads();
}

__global__ void __launch_bounds__(NT, 1)
gat_persistent(const float* __restrict__ h, const int* __restrict__ adj,
               const float* __restrict__ w, const float* __restrict__ v,
               float* __restrict__ out, int N)
{
    extern __shared__ __align__(16) float dyn[];
    float* s_hwC = dyn;                          // CAP_STAGE * NOUT floats
    float* s_w   = dyn + CAP_STAGE * NOUT;       // [32 warps][2 rows][256 slots]

    __shared__ __align__(16) float s_wv2[NIN];
    __shared__ float s_red[NT];                  // used by phase F only
    __shared__ float s_bmax[32];
    __shared__ int   s_wsum[32], s_woff[32];
    __shared__ int   s_idx[CAP];
    __shared__ float s_e[CAP];
    __shared__ __align__(16) float s_h[NIN];
    __shared__ float s_part[8][NOUT];
    __shared__ float s_acc[NOUT];
    __shared__ int   s_list[512];
    __shared__ float s_wl[512];
    __shared__ int   s_cnt;

    const int t    = threadIdx.x;
    const int lane = t & 31;
    const int wid  = t >> 5;
    const int blk  = blockIdx.x;

    // ---- Phase A: wv2 = w @ v2, redundant per block ----
    {
        int k = t >> 2, part = t & 3;           // 256 k's x 4 partials
        const float4* wr = (const float4*)(w + (size_t)k * NOUT + part * 32);
        const float4* v2 = (const float4*)(v + NOUT + part * 32);
        float a0 = 0.f, a1 = 0.f;
        #pragma unroll
        for (int q = 0; q < 8; ++q) {
            float4 wa = wr[q], va = v2[q];
            a0 = fmaf(wa.x, va.x, a0); a1 = fmaf(wa.y, va.y, a1);
            a0 = fmaf(wa.z, va.z, a0); a1 = fmaf(wa.w, va.w, a1);
        }
        float p = a0 + a1;
        p += __shfl_xor_sync(0xffffffffu, p, 1);
        p += __shfl_xor_sync(0xffffffffu, p, 2);
        if (part == 0) s_wv2[k] = p;
    }
    __syncthreads();

    // ---- Phase B: hw2 for both of this warp's rows + per-block max ----
    const int row0 = blk * 32 + wid;
    const int row1 = row0 + NB * 32;            // 4736 apart
    const bool v1  = row1 < N;
    {
        const float4* wv = (const float4*)s_wv2;
        float4 wa = wv[lane], wb = wv[lane + 32];
        const float4* h0 = (const float4*)(h + (size_t)row0 * NIN);
        float4 a0 = h0[lane], b0 = h0[lane + 32];
        float4 a1 = make_float4(0.f, 0.f, 0.f, 0.f), b1 = a1;
        if (v1) {
            const float4* h1 = (const float4*)(h + (size_t)row1 * NIN);
            a1 = h1[lane]; b1 = h1[lane + 32];
        }
        float acc0 = 0.f, acc1 = 0.f;
        acc0 = fmaf(a0.x, wa.x, acc0); acc1 = fmaf(a1.x, wa.x, acc1);
        acc0 = fmaf(a0.y, wa.y, acc0); acc1 = fmaf(a1.y, wa.y, acc1);
        acc0 = fmaf(a0.z, wa.z, acc0); acc1 = fmaf(a1.z, wa.z, acc1);
        acc0 = fmaf(a0.w, wa.w, acc0); acc1 = fmaf(a1.w, wa.w, acc1);
        acc0 = fmaf(b0.x, wb.x, acc0); acc1 = fmaf(b1.x, wb.x, acc1);
        acc0 = fmaf(b0.y, wb.y, acc0); acc1 = fmaf(b1.y, wb.y, acc1);
        acc0 = fmaf(b0.z, wb.z, acc0); acc1 = fmaf(b1.z, wb.z, acc1);
        acc0 = fmaf(b0.w, wb.w, acc0); acc1 = fmaf(b1.w, wb.w, acc1);
        for (int d = 16; d; d >>= 1) {
            acc0 += __shfl_down_sync(0xffffffffu, acc0, d);
            acc1 += __shfl_down_sync(0xffffffffu, acc1, d);
        }
        if (lane == 0) {
            g_hw2[row0] = acc0;
            float mx = acc0;
            if (v1) { g_hw2[row1] = acc1; mx = fmaxf(mx, acc1); }
            s_bmax[wid] = mx;
        }
        __syncthreads();
        if (wid == 0) {
            float m32 = s_bmax[lane];
            for (int d = 16; d; d >>= 1)
                m32 = fmaxf(m32, __shfl_xor_sync(0xffffffffu, m32, d));
            if (lane == 0) atomicMax(&g_M_key, fkey(m32));
        }
    }
    gbar(NB * 1);

    // ---- Phase C (redundant per block): threshold scan + compaction ----
    float Mthr;
    int   cnt;
    {
        float M   = fkey_inv(g_M_key);
        float thr = M - DELTA_CAND;
        Mthr      = M - (DELTA_CAND - KEEP);

        int j0 = t * 8;                         // N == NT*8
        float hv[8];
        #pragma unroll
        for (int r = 0; r < 8; ++r) hv[r] = (j0 + r < N) ? g_hw2[j0 + r] : -INFINITY;
        int c = 0;
        #pragma unroll
        for (int r = 0; r < 8; ++r) if (hv[r] >= thr) c++;
        int inc = c;
        for (int d = 1; d < 32; d <<= 1) {
            int vv = __shfl_up_sync(0xffffffffu, inc, d);
            if (lane >= d) inc += vv;
        }
        if (lane == 31) s_wsum[wid] = inc;
        __syncthreads();
        if (wid == 0) {
            int vv = s_wsum[lane];
            int winc = vv;
            for (int d = 1; d < 32; d <<= 1) {
                int u = __shfl_up_sync(0xffffffffu, winc, d);
                if (lane >= d) winc += u;
            }
            s_woff[lane] = winc - vv;
            if (lane == 31) s_cnt = winc;
        }
        __syncthreads();
        cnt = s_cnt;
        if (cnt <= CAP) {
            int pos = s_woff[wid] + (inc - c);
            #pragma unroll
            for (int r = 0; r < 8; ++r) {
                if (hv[r] >= thr) { s_idx[pos] = j0 + r; s_e[pos] = hv[r]; pos++; }
            }
        } else {
            cnt = 0;                            // overflow: full exact fallback
            Mthr = INFINITY;
        }
        __syncthreads();
    }

    // ---- Phase D (NO barrier): blocks < cnt compute their candidate GEMV;
    // all other blocks fall straight through to the adj gather. ----
    {
        int col = t & 127, kg = t >> 7;
        for (int c = blk; c < cnt; c += NB) {
            if (t < NIN / 4)
                ((float4*)s_h)[t] = ((const float4*)(h + (size_t)s_idx[c] * NIN))[t];
            __syncthreads();
            const float* wc = w + (size_t)(kg * 32) * NOUT + col;
            float a0 = 0.f, a1 = 0.f, a2 = 0.f, a3 = 0.f;
            #pragma unroll
            for (int b = 0; b < 2; ++b) {
                float wv[16];
                #pragma unroll
                for (int u = 0; u < 16; ++u)
                    wv[u] = wc[(size_t)(b * 16 + u) * NOUT];
                #pragma unroll
                for (int u = 0; u < 16; u += 4) {
                    a0 = fmaf(s_h[kg * 32 + b * 16 + u],     wv[u],     a0);
                    a1 = fmaf(s_h[kg * 32 + b * 16 + u + 1], wv[u + 1], a1);
                    a2 = fmaf(s_h[kg * 32 + b * 16 + u + 2], wv[u + 2], a2);
                    a3 = fmaf(s_h[kg * 32 + b * 16 + u + 3], wv[u + 3], a3);
                }
            }
            s_part[kg][col] = (a0 + a1) + (a2 + a3);
            __syncthreads();
            if (t < NOUT) {
                float s = 0.f;
                #pragma unroll
                for (int g = 0; g < 8; ++g) s += s_part[g][t];
                g_hwC[(size_t)c * NOUT + t] = s;
            }
            __syncthreads();
        }
    }

    // ---- Phase E-gather: adj gather + softmax weights for both rows,
    // weights parked in smem; overlaps D and the barrier wait. ----
    float den0 = 0.f, den1 = 0.f;
    bool  flag0, flag1 = false;
    {
        const int* a0p = adj + (size_t)row0 * N;
        const int* a1p = adj + (size_t)row1 * N;
        float e0[8], e1[8];
        #pragma unroll
        for (int g = 0; g < 8; ++g) {
            int k = g * 32 + lane;
            bool in = k < cnt;
            e0[g] = -INFINITY; e1[g] = -INFINITY;
            if (in) {
                int j = s_idx[k];
                float ee = s_e[k];
                if (a0p[j] > 0) e0[g] = ee;
                if (v1 && a1p[j] > 0) e1[g] = ee;
            }
        }
        // row0
        float m0 = e0[0];
        #pragma unroll
        for (int g = 1; g < 8; ++g) m0 = fmaxf(m0, e0[g]);
        for (int d = 16; d; d >>= 1) m0 = fmaxf(m0, __shfl_xor_sync(0xffffffffu, m0, d));
        bool live0 = m0 > -INFINITY;
        float* sw0 = s_w + (size_t)(wid * 2 + 0) * 256;
        #pragma unroll
        for (int g = 0; g < 8; ++g) {
            float wv = live0 ? __expf(e0[g] - m0) : 0.f;   // -inf -> 0
            den0 += wv;
            sw0[g * 32 + lane] = wv;
        }
        for (int d = 16; d; d >>= 1) den0 += __shfl_xor_sync(0xffffffffu, den0, d);
        flag0 = !(m0 >= Mthr);
        if (flag0 && lane == 0) {
            int p = atomicAdd(&g_flag_count, 1);
            g_flag_list[p] = row0;
        }
        // row1
        if (v1) {
            float m1 = e1[0];
            #pragma unroll
            for (int g = 1; g < 8; ++g) m1 = fmaxf(m1, e1[g]);
            for (int d = 16; d; d >>= 1) m1 = fmaxf(m1, __shfl_xor_sync(0xffffffffu, m1, d));
            bool live1 = m1 > -INFINITY;
            float* sw1 = s_w + (size_t)(wid * 2 + 1) * 256;
            #pragma unroll
            for (int g = 0; g < 8; ++g) {
                float wv = live1 ? __expf(e1[g] - m1) : 0.f;
                den1 += wv;
                sw1[g * 32 + lane] = wv;
            }
            for (int d = 16; d; d >>= 1) den1 += __shfl_xor_sync(0xffffffffu, den1, d);
            flag1 = !(m1 >= Mthr);
            if (flag1 && lane == 0) {
                int p = atomicAdd(&g_flag_count, 1);
                g_flag_list[p] = row1;
            }
        }
    }
    gbar(NB * 2);

    // ---- Stage hwC into smem, then accumulate + store both rows ----
    const int nstage = min(cnt, CAP_STAGE);
    for (int i = t; i < nstage * (NOUT / 4); i += NT)
        ((float4*)s_hwC)[i] = ((const float4*)g_hwC)[i];
    __syncthreads();
    {
        const float4* hwC4 = (const float4*)g_hwC;
        const float4* sC4  = (const float4*)s_hwC;
        #pragma unroll
        for (int r = 0; r < 2; ++r) {
            int row = (r == 0) ? row0 : row1;
            if (r == 1 && !v1) break;
            const float* swr = s_w + (size_t)(wid * 2 + r) * 256;
            float4 acc = make_float4(0.f, 0.f, 0.f, 0.f);
            for (int g = 0; g < 8 && g * 32 < cnt; ++g) {
                float wl = swr[g * 32 + lane];
                unsigned msk = __ballot_sync(0xffffffffu, wl != 0.f);
                while (msk) {
                    int b = __ffs(msk) - 1;
                    msk &= msk - 1;
                    float wb = __shfl_sync(0xffffffffu, wl, b);
                    int c = g * 32 + b;
                    float4 hv = (c < nstage) ? sC4[c * (NOUT / 4) + lane]
                                             : hwC4[(size_t)c * (NOUT / 4) + lane];
                    acc.x = fmaf(wb, hv.x, acc.x);
                    acc.y = fmaf(wb, hv.y, acc.y);
                    acc.z = fmaf(wb, hv.z, acc.z);
                    acc.w = fmaf(wb, hv.w, acc.w);
                }
            }
            bool flag = (r == 0) ? flag0 : flag1;
            float den = (r == 0) ? den0 : den1;
            float inv = flag ? 0.f : (1.f / den);
            float4 o = make_float4(acc.x * inv, acc.y * inv, acc.z * inv, acc.w * inv);
            ((float4*)out)[(size_t)row * (NOUT / 4) + lane] = o;
        }
    }
    gbar(NB * 3);

    // ---- Phase F: exact fallback for flagged rows (statistically ~0) ----
    {
        int fc = g_flag_count;
        for (int f = blk; f < fc; f += NB) {
            int row = g_flag_list[f];
            const int* adjrow = adj + (size_t)row * N;

            float lm = -INFINITY;
            for (int j = t; j < N; j += NT)
                if (adjrow[j] > 0) lm = fmaxf(lm, g_hw2[j]);
            s_red[t] = lm;
            __syncthreads();
            for (int s = 512; s; s >>= 1) {
                if (t < s) s_red[t] = fmaxf(s_red[t], s_red[t + s]);
                __syncthreads();
            }
            float m = s_red[0];
            __syncthreads();
            bool uni = !(m > -INFINITY);  // fully masked row -> uniform softmax

            if (t < NOUT) s_acc[t] = 0.f;
            float denom = 0.f;
            int col = t & 127, kg = t >> 7;
            for (int cb = 0; cb < N; cb += 512) {
                if (t == 0) s_cnt = 0;
                __syncthreads();
                int ce = min(cb + 512, N);
                for (int j = cb + t; j < ce; j += NT) {
                    bool act = uni ? true : (adjrow[j] > 0 && g_hw2[j] >= m - KEEP);
                    if (act) {
                        int p = atomicAdd(&s_cnt, 1);
                        s_list[p] = j;
                        s_wl[p]   = uni ? 1.f : expf(g_hw2[j] - m);
                    }
                }
                __syncthreads();
                int L = s_cnt;
                for (int l = 0; l < L; ++l) {
                    int j = s_list[l];
                    float wl = s_wl[l];
                    if (t < NIN / 4)
                        ((float4*)s_h)[t] = ((const float4*)(h + (size_t)j * NIN))[t];
                    __syncthreads();
                    const float* wc = w + (size_t)(kg * 32) * NOUT + col;
                    float a0 = 0.f, a1 = 0.f, a2 = 0.f, a3 = 0.f;
                    #pragma unroll
                    for (int b = 0; b < 2; ++b) {
                        float wv[16];
                        #pragma unroll
                        for (int u = 0; u < 16; ++u)
                            wv[u] = wc[(size_t)(b * 16 + u) * NOUT];
                        #pragma unroll
                        for (int u = 0; u < 16; u += 4) {
                            a0 = fmaf(s_h[kg * 32 + b * 16 + u],     wv[u],     a0);
                            a1 = fmaf(s_h[kg * 32 + b * 16 + u + 1], wv[u + 1], a1);
                            a2 = fmaf(s_h[kg * 32 + b * 16 + u + 2], wv[u + 2], a2);
                            a3 = fmaf(s_h[kg * 32 + b * 16 + u + 3], wv[u + 3], a3);
                        }
                    }
                    s_part[kg][col] = (a0 + a1) + (a2 + a3);
                    __syncthreads();
                    if (t < NOUT) {
                        float s = 0.f;
                        #pragma unroll
                        for (int g = 0; g < 8; ++g) s += s_part[g][t];
                        s_acc[t] += wl * s;
                    }
                    denom += wl;
                    __syncthreads();
                }
                __syncthreads();
            }
            if (t < NOUT) out[(size_t)row * NOUT + t] = s_acc[t] / denom;
            __syncthreads();
        }
    }

    // ---- Epilogue: last block resets globals for next graph replay ----
    __syncthreads();
    if (t == 0) {
        unsigned r = atomicAdd(&g_done_cnt, 1u);
        if (r == NB - 1) {
            *(volatile int*)&g_flag_count      = 0;
            *(volatile unsigned*)&g_M_key      = 0;
            *(volatile unsigned*)&g_done_cnt   = 0;
            *(volatile unsigned*)&g_bar_cnt    = 0;
            __threadfence();
        }
    }
}

extern "C" void kernel_launch(void* const* d_in, const int* in_sizes, int n_in,
                              void* d_out, int out_size) {
    const float* h   = (const float*)d_in[0];
    const int*   adj = (const int*)d_in[1];
    const float* w   = (const float*)d_in[2];
    const float* v   = (const float*)d_in[3];
    float* out = (float*)d_out;

    int nout = in_sizes[3] / 2;        // 128
    int nin  = in_sizes[2] / nout;     // 256
    int N    = in_sizes[0] / nin;      // 8192
    (void)nout; (void)nin; (void)n_in; (void)out_size;

    const int dyn_smem = (CAP_STAGE * NOUT + 32 * 2 * 256) * sizeof(float); // 128 KB
    cudaFuncSetAttribute(gat_persistent,
                         cudaFuncAttributeMaxDynamicSharedMemorySize, dyn_smem);
    gat_persistent<<<NB, NT, dyn_smem>>>(h, adj, w, v, out, N);
}